// round 4
// baseline (speedup 1.0000x reference)
#include <cuda_runtime.h>
#include <cuda_bf16.h>
#include <cstdint>

// ---------------------------------------------------------------------------
// AttentionEncoderLayer: B=4, C=8, F=2048, H=512, NH=8, dh=64, Hf=1024
//   M = F*B = 8192 query rows; key/value flat [65536,512];
//   query row m attends KV rows [8m, 8m+8).
// GEMMs: HMMA (mma.sync bf16) with 3-pass split-bf16 (fp32-grade accuracy).
// Tile: BM=128 x BN=256, BK=64, 8 warps, warp tile 64x64, double-buffered
// smem, convert/STS overlapped into the MMA loop.
// ---------------------------------------------------------------------------

#define M_Q   8192
#define M_KV  65536
#define Hdim  512
#define HF    1024

__device__ float g_Qp [M_Q  * Hdim];
__device__ float g_Kp [M_KV * Hdim];
__device__ float g_Vp [M_KV * Hdim];
__device__ float g_att[M_Q  * Hdim];
__device__ float g_x  [M_Q  * Hdim];
__device__ float g_h1 [M_Q  * Hdim];
__device__ float g_f1 [M_Q  * HF  ];

// ---------------- helpers ----------------
__device__ __forceinline__ uint32_t smem_u32(const void* p) {
    uint32_t a;
    asm("{ .reg .u64 t; cvta.to.shared.u64 t, %1; cvt.u32.u64 %0, t; }" : "=r"(a) : "l"(p));
    return a;
}

__device__ __forceinline__ void ldsm4(uint32_t* r, uint32_t addr) {
    asm volatile("ldmatrix.sync.aligned.m8n8.x4.shared.b16 {%0,%1,%2,%3}, [%4];"
                 : "=r"(r[0]), "=r"(r[1]), "=r"(r[2]), "=r"(r[3]) : "r"(addr));
}

__device__ __forceinline__ void mma16816(float* d, const uint32_t* a, const uint32_t* b) {
    asm volatile("mma.sync.aligned.m16n8k16.row.col.f32.bf16.bf16.f32 "
                 "{%0,%1,%2,%3}, {%4,%5,%6,%7}, {%8,%9}, {%0,%1,%2,%3};"
                 : "+f"(d[0]), "+f"(d[1]), "+f"(d[2]), "+f"(d[3])
                 : "r"(a[0]), "r"(a[1]), "r"(a[2]), "r"(a[3]), "r"(b[0]), "r"(b[1]));
}

// ---------------------------------------------------------------------------
// smem layout per buffer: Ah(16K) Al(16K) Bh(32K) Bl(32K) = 96KB, x2 buffers
// ---------------------------------------------------------------------------
#define AH_OFF 0
#define AL_OFF 16384
#define BH_OFF 32768
#define BL_OFF 65536
#define BUF_STRIDE 98304
#define SMEM_GEMM (2 * BUF_STRIDE)   // 196608

// global fp32 -> 8 x float4 per thread (one 128x64 fp32 tile across 256 thr)
__device__ __forceinline__ void ldg8(const float* __restrict__ src, int ldk,
                                     int row0, int k0, int g, int c4, float4* v)
{
#pragma unroll
    for (int i = 0; i < 8; i++)
        v[i] = *(const float4*)(src + (size_t)(row0 + g * 8 + i) * ldk + k0 + c4 * 4);
}

// registers -> bf16 hi/lo swizzled smem tiles (128 rows x 64 cols)
__device__ __forceinline__ void cvsts8(const float4* v, char* __restrict__ hb,
                                       char* __restrict__ lb, int g, int c4)
{
#pragma unroll
    for (int i = 0; i < 8; i++) {
        const int r = g * 8 + i;
        const float4 x = v[i];

        uint32_t h01, h23;
        asm("cvt.rn.bf16x2.f32 %0, %1, %2;" : "=r"(h01) : "f"(x.y), "f"(x.x));
        asm("cvt.rn.bf16x2.f32 %0, %1, %2;" : "=r"(h23) : "f"(x.w), "f"(x.z));

        const float hf0 = __uint_as_float(h01 << 16);
        const float hf1 = __uint_as_float(h01 & 0xffff0000u);
        const float hf2 = __uint_as_float(h23 << 16);
        const float hf3 = __uint_as_float(h23 & 0xffff0000u);

        uint32_t l01, l23;
        asm("cvt.rn.bf16x2.f32 %0, %1, %2;" : "=r"(l01) : "f"(x.y - hf1), "f"(x.x - hf0));
        asm("cvt.rn.bf16x2.f32 %0, %1, %2;" : "=r"(l23) : "f"(x.w - hf3), "f"(x.z - hf2));

        const int off = r * 128 + ((c4 * 8) ^ ((r & 7) << 4));
        *(uint2*)(hb + off) = make_uint2(h01, h23);
        *(uint2*)(lb + off) = make_uint2(l01, l23);
    }
}

__global__ __launch_bounds__(256, 1)
void gemm_mma(const float* __restrict__ A, const float* __restrict__ W,
              const float* __restrict__ bias, float* __restrict__ C,
              int M, int N, int K, int relu)
{
    extern __shared__ char smem[];
    const uint32_t sb = smem_u32(smem);

    const int tid = threadIdx.x;
    const int l   = tid & 31;
    const int w   = tid >> 5;
    const int mw  = w >> 2;      // 0..1 : 64-row half
    const int nw  = w & 3;       // 0..3 : 64-col quarter
    const int m0  = blockIdx.y * 128;
    const int n0  = blockIdx.x * 256;
    const int g   = tid >> 4;
    const int c4  = tid & 15;

    // ldmatrix lane geometry
    const uint32_t swz  = (uint32_t)((l & 7) << 4);
    const uint32_t ak   = (uint32_t)((l >> 4) << 4);
    const uint32_t bk   = (uint32_t)(((l >> 3) & 1) << 4);
    const uint32_t rowA = (uint32_t)((mw * 64 + (l & 15)) * 128);
    const uint32_t rowB = (uint32_t)((nw * 64 + ((l >> 4) << 3) + (l & 7)) * 128);

    float acc[4][8][4];
#pragma unroll
    for (int i = 0; i < 4; i++)
#pragma unroll
        for (int j = 0; j < 8; j++)
#pragma unroll
            for (int q = 0; q < 4; q++) acc[i][j][q] = 0.f;

    const int NC = K >> 6;

    float4 va[8], vb1[8], vb2[8];

    // prologue: chunk 0 -> buffer 0
    ldg8(A, K, m0,       0, g, c4, va);
    ldg8(W, K, n0,       0, g, c4, vb1);
    ldg8(W, K, n0 + 128, 0, g, c4, vb2);
    cvsts8(va,  smem + AH_OFF,         smem + AL_OFF,         g, c4);
    cvsts8(vb1, smem + BH_OFF,         smem + BL_OFF,         g, c4);
    cvsts8(vb2, smem + BH_OFF + 16384, smem + BL_OFF + 16384, g, c4);
    __syncthreads();

    for (int c = 0; c < NC; c++) {
        const int b    = c & 1;
        const bool more = (c + 1 < NC);
        const uint32_t bufb = sb + b * BUF_STRIDE;
        char* bufn = smem + (b ^ 1) * BUF_STRIDE;

        if (more) {
            ldg8(A, K, m0, (c + 1) << 6, g, c4, va);
            ldg8(W, K, n0, (c + 1) << 6, g, c4, vb1);
        }

#pragma unroll
        for (int kk = 0; kk < 4; kk++) {
            const uint32_t kbB = ((uint32_t)(kk * 32) | bk) ^ swz;
            const uint32_t kbA = ((uint32_t)(kk * 32) | ak) ^ swz;

            uint32_t bh[16], bl[16];
            const uint32_t bB = bufb + BH_OFF + rowB + kbB;
#pragma unroll
            for (int j = 0; j < 4; j++) {
                ldsm4(bh + 4 * j, bB + j * 2048);
                ldsm4(bl + 4 * j, bB + j * 2048 + (BL_OFF - BH_OFF));
            }

            const uint32_t aB = bufb + AH_OFF + rowA + kbA;
#pragma unroll
            for (int mt = 0; mt < 4; mt++) {
                uint32_t ah[4], al[4];
                ldsm4(ah, aB + mt * 2048);
                ldsm4(al, aB + mt * 2048 + (AL_OFF - AH_OFF));
#pragma unroll
                for (int nt = 0; nt < 8; nt++) mma16816(acc[mt][nt], ah, bh + nt * 2);
#pragma unroll
                for (int nt = 0; nt < 8; nt++) mma16816(acc[mt][nt], ah, bl + nt * 2);
#pragma unroll
                for (int nt = 0; nt < 8; nt++) mma16816(acc[mt][nt], al, bh + nt * 2);
            }

            if (kk == 1 && more) {
                // overlap: stash next chunk A + B-half1, then fetch B-half2
                cvsts8(va,  bufn + AH_OFF, bufn + AL_OFF, g, c4);
                cvsts8(vb1, bufn + BH_OFF, bufn + BL_OFF, g, c4);
                ldg8(W, K, n0 + 128, (c + 1) << 6, g, c4, vb2);
            }
        }

        if (more)
            cvsts8(vb2, bufn + BH_OFF + 16384, bufn + BL_OFF + 16384, g, c4);
        __syncthreads();
    }

    // epilogue: registers -> C with bias (+relu)
    const int row_base = m0 + mw * 64 + (l >> 2);
    const int col_base = n0 + nw * 64 + 2 * (l & 3);
#pragma unroll
    for (int mt = 0; mt < 4; mt++) {
        const int row = row_base + mt * 16;
#pragma unroll
        for (int nt = 0; nt < 8; nt++) {
            const int col = col_base + nt * 8;
            const float2 bv = *(const float2*)(bias + col);
            float2 r0, r1;
            r0.x = acc[mt][nt][0] + bv.x;  r0.y = acc[mt][nt][1] + bv.y;
            r1.x = acc[mt][nt][2] + bv.x;  r1.y = acc[mt][nt][3] + bv.y;
            if (relu) {
                r0.x = fmaxf(r0.x, 0.f); r0.y = fmaxf(r0.y, 0.f);
                r1.x = fmaxf(r1.x, 0.f); r1.y = fmaxf(r1.y, 0.f);
            }
            *(float2*)(C + (size_t)row * N + col)       = r0;
            *(float2*)(C + (size_t)(row + 8) * N + col) = r1;
        }
    }
}

// ---------------------------------------------------------------------------
// Attention: one block per query row m, warp = head. S=8, dh=64, scale=0.125
// ---------------------------------------------------------------------------
__global__ __launch_bounds__(256)
void attn_kernel(const float* __restrict__ Qp, const float* __restrict__ Kp,
                 const float* __restrict__ Vp, float* __restrict__ out)
{
    const int m = blockIdx.x;
    const int w = threadIdx.x >> 5;
    const int l = threadIdx.x & 31;

    const size_t qoff = (size_t)m * Hdim + w * 64;
    const float q0 = Qp[qoff + l];
    const float q1 = Qp[qoff + l + 32];

    float s[8];
#pragma unroll
    for (int c = 0; c < 8; c++) {
        const float* k = Kp + ((size_t)m * 8 + c) * Hdim + w * 64;
        float p = q0 * k[l] + q1 * k[l + 32];
#pragma unroll
        for (int o = 16; o > 0; o >>= 1)
            p += __shfl_xor_sync(0xffffffffu, p, o);
        s[c] = p * 0.125f;
    }

    float mx = s[0];
#pragma unroll
    for (int c = 1; c < 8; c++) mx = fmaxf(mx, s[c]);
    float sum = 0.f;
#pragma unroll
    for (int c = 0; c < 8; c++) { s[c] = __expf(s[c] - mx); sum += s[c]; }
    const float inv = 1.f / sum;

    float o0 = 0.f, o1 = 0.f;
#pragma unroll
    for (int c = 0; c < 8; c++) {
        const float* v = Vp + ((size_t)m * 8 + c) * Hdim + w * 64;
        const float p = s[c] * inv;
        o0 += p * v[l];
        o1 += p * v[l + 32];
    }
    out[qoff + l]      = o0;
    out[qoff + l + 32] = o1;
}

// ---------------------------------------------------------------------------
// LayerNorm(x + r) over H=512, one block (256 threads) per row.
// warp-shuffle reduction, 2 barriers.
// ---------------------------------------------------------------------------
__global__ __launch_bounds__(256)
void ln_residual_kernel(const float* __restrict__ x, const float* __restrict__ r,
                        const float* __restrict__ g, const float* __restrict__ bt,
                        float* __restrict__ out)
{
    __shared__ float red[16];
    const int m = blockIdx.x;
    const int t = threadIdx.x;
    const int l = t & 31;
    const int w = t >> 5;
    const size_t base = (size_t)m * Hdim;

    const float s0 = x[base + t]       + r[base + t];
    const float s1 = x[base + t + 256] + r[base + t + 256];

    float v = s0 + s1;
#pragma unroll
    for (int o = 16; o > 0; o >>= 1) v += __shfl_xor_sync(0xffffffffu, v, o);
    if (l == 0) red[w] = v;
    __syncthreads();
    float mean = 0.f;
#pragma unroll
    for (int i = 0; i < 8; i++) mean += red[i];
    mean *= (1.f / 512.f);

    const float d0 = s0 - mean, d1 = s1 - mean;
    float vv = d0 * d0 + d1 * d1;
#pragma unroll
    for (int o = 16; o > 0; o >>= 1) vv += __shfl_xor_sync(0xffffffffu, vv, o);
    if (l == 0) red[8 + w] = vv;
    __syncthreads();
    float var = 0.f;
#pragma unroll
    for (int i = 0; i < 8; i++) var += red[8 + i];
    var *= (1.f / 512.f);
    const float rstd = rsqrtf(var + 1e-5f);

    out[base + t]       = d0 * rstd * g[t]       + bt[t];
    out[base + t + 256] = d1 * rstd * g[t + 256] + bt[t + 256];
}

// ---------------------------------------------------------------------------
extern "C" void kernel_launch(void* const* d_in, const int* in_sizes, int n_in,
                              void* d_out, int out_size)
{
    (void)in_sizes; (void)n_in; (void)out_size;
    const float* query = (const float*)d_in[0];
    const float* key   = (const float*)d_in[1];
    const float* value = (const float*)d_in[2];
    const float* Wq    = (const float*)d_in[3];
    const float* bq    = (const float*)d_in[4];
    const float* Wk    = (const float*)d_in[5];
    const float* bk    = (const float*)d_in[6];
    const float* Wv    = (const float*)d_in[7];
    const float* bv    = (const float*)d_in[8];
    const float* Wo    = (const float*)d_in[9];
    const float* bo    = (const float*)d_in[10];
    const float* ln1g  = (const float*)d_in[11];
    const float* ln1b  = (const float*)d_in[12];
    const float* W1    = (const float*)d_in[13];
    const float* b1    = (const float*)d_in[14];
    const float* W2    = (const float*)d_in[15];
    const float* b2    = (const float*)d_in[16];
    const float* ln2g  = (const float*)d_in[17];
    const float* ln2b  = (const float*)d_in[18];
    float* out = (float*)d_out;

    float *Qp, *Kp, *Vp, *att, *x, *h1, *f1;
    cudaGetSymbolAddress((void**)&Qp,  g_Qp);
    cudaGetSymbolAddress((void**)&Kp,  g_Kp);
    cudaGetSymbolAddress((void**)&Vp,  g_Vp);
    cudaGetSymbolAddress((void**)&att, g_att);
    cudaGetSymbolAddress((void**)&x,   g_x);
    cudaGetSymbolAddress((void**)&h1,  g_h1);
    cudaGetSymbolAddress((void**)&f1,  g_f1);

    cudaFuncSetAttribute(gemm_mma, cudaFuncAttributeMaxDynamicSharedMemorySize, SMEM_GEMM);

    // Q/K/V projections
    gemm_mma<<<dim3(Hdim/256, M_Q /128), 256, SMEM_GEMM>>>(query, Wq, bq, Qp, M_Q,  Hdim, Hdim, 0);
    gemm_mma<<<dim3(Hdim/256, M_KV/128), 256, SMEM_GEMM>>>(key,   Wk, bk, Kp, M_KV, Hdim, Hdim, 0);
    gemm_mma<<<dim3(Hdim/256, M_KV/128), 256, SMEM_GEMM>>>(value, Wv, bv, Vp, M_KV, Hdim, Hdim, 0);

    // attention (S=8 per row)
    attn_kernel<<<M_Q, 256>>>(Qp, Kp, Vp, att);

    // O projection + residual + LN1
    gemm_mma<<<dim3(Hdim/256, M_Q/128), 256, SMEM_GEMM>>>(att, Wo, bo, x, M_Q, Hdim, Hdim, 0);
    ln_residual_kernel<<<M_Q, 256>>>(x, query, ln1g, ln1b, h1);

    // FFN + residual + LN2 (writes final output)
    gemm_mma<<<dim3(HF  /256, M_Q/128), 256, SMEM_GEMM>>>(h1, W1, b1, f1, M_Q, HF,   Hdim, 1);
    gemm_mma<<<dim3(Hdim/256, M_Q/128), 256, SMEM_GEMM>>>(f1, W2, b2, x,  M_Q, Hdim, HF,   0);
    ln_residual_kernel<<<M_Q, 256>>>(x, h1, ln2g, ln2b, out);
}

// round 5
// speedup vs baseline: 1.2280x; 1.2280x over previous
#include <cuda_runtime.h>
#include <cuda_bf16.h>
#include <cstdint>

// ---------------------------------------------------------------------------
// AttentionEncoderLayer: B=4, C=8, F=2048, H=512, NH=8, dh=64, Hf=1024
//   M = F*B = 8192 query rows; key/value flat [65536,512];
//   query row m attends KV rows [8m, 8m+8).
// GEMMs: split-bf16 HMMA, 3 passes (Ah*Bh + Ah*Bl + Al*Bh), fp32 accum.
// Inputs pre-split into hi/lo bf16 planes by a prepass kernel; GEMM mainloop
// is pure cp.async + ldmatrix + mma (no conversion, no register staging).
// Tile BM=128 x BN=256 x BK=64, 8 warps (warp tile 64x64), double buffered.
// ---------------------------------------------------------------------------

#define M_Q   8192
#define M_KV  65536
#define Hdim  512
#define HF    1024

typedef __nv_bfloat16 bf16;

// fp32 intermediates
__device__ float g_Qp [M_Q  * Hdim];
__device__ float g_Kp [M_KV * Hdim];
__device__ float g_Vp [M_KV * Hdim];
__device__ float g_att[M_Q  * Hdim];
__device__ float g_x  [M_Q  * Hdim];
__device__ float g_h1 [M_Q  * Hdim];
__device__ float g_f1 [M_Q  * HF  ];

// hi/lo bf16 planes (GEMM operands)
__device__ bf16 g_q_h [M_Q  * Hdim];  __device__ bf16 g_q_l [M_Q  * Hdim];
__device__ bf16 g_k_h [M_KV * Hdim];  __device__ bf16 g_k_l [M_KV * Hdim];
__device__ bf16 g_v_h [M_KV * Hdim];  __device__ bf16 g_v_l [M_KV * Hdim];
__device__ bf16 g_at_h[M_Q  * Hdim];  __device__ bf16 g_at_l[M_Q  * Hdim];
__device__ bf16 g_h1_h[M_Q  * Hdim];  __device__ bf16 g_h1_l[M_Q  * Hdim];
__device__ bf16 g_f1_h[M_Q  * HF  ];  __device__ bf16 g_f1_l[M_Q  * HF  ];
__device__ bf16 g_wq_h[Hdim * Hdim];  __device__ bf16 g_wq_l[Hdim * Hdim];
__device__ bf16 g_wk_h[Hdim * Hdim];  __device__ bf16 g_wk_l[Hdim * Hdim];
__device__ bf16 g_wv_h[Hdim * Hdim];  __device__ bf16 g_wv_l[Hdim * Hdim];
__device__ bf16 g_wo_h[Hdim * Hdim];  __device__ bf16 g_wo_l[Hdim * Hdim];
__device__ bf16 g_w1_h[HF * Hdim];    __device__ bf16 g_w1_l[HF * Hdim];
__device__ bf16 g_w2_h[Hdim * HF];    __device__ bf16 g_w2_l[Hdim * HF];

// ---------------- helpers ----------------
__device__ __forceinline__ uint32_t smem_u32(const void* p) {
    uint32_t a;
    asm("{ .reg .u64 t; cvta.to.shared.u64 t, %1; cvt.u32.u64 %0, t; }" : "=r"(a) : "l"(p));
    return a;
}
__device__ __forceinline__ void ldsm4(uint32_t* r, uint32_t addr) {
    asm volatile("ldmatrix.sync.aligned.m8n8.x4.shared.b16 {%0,%1,%2,%3}, [%4];"
                 : "=r"(r[0]), "=r"(r[1]), "=r"(r[2]), "=r"(r[3]) : "r"(addr));
}
__device__ __forceinline__ void mma16816(float* d, const uint32_t* a, const uint32_t* b) {
    asm volatile("mma.sync.aligned.m16n8k16.row.col.f32.bf16.bf16.f32 "
                 "{%0,%1,%2,%3}, {%4,%5,%6,%7}, {%8,%9}, {%0,%1,%2,%3};"
                 : "+f"(d[0]), "+f"(d[1]), "+f"(d[2]), "+f"(d[3])
                 : "r"(a[0]), "r"(a[1]), "r"(a[2]), "r"(a[3]), "r"(b[0]), "r"(b[1]));
}
__device__ __forceinline__ void cp16(uint32_t dst, const void* src) {
    asm volatile("cp.async.cg.shared.global [%0], [%1], 16;" :: "r"(dst), "l"(src));
}
#define CP_COMMIT() asm volatile("cp.async.commit_group;" ::: "memory")
#define CP_WAIT0()  asm volatile("cp.async.wait_group 0;" ::: "memory")

// ---------------------------------------------------------------------------
// prepass: fp32 -> (hi, lo) bf16 planes.  n4 = elements/4.
// ---------------------------------------------------------------------------
__global__ __launch_bounds__(256)
void cvt_hl(const float4* __restrict__ src, uint2* __restrict__ hi,
            uint2* __restrict__ lo, int n4)
{
    const int i = blockIdx.x * 256 + threadIdx.x;
    if (i >= n4) return;
    const float4 x = src[i];

    uint32_t h01, h23;
    asm("cvt.rn.bf16x2.f32 %0, %1, %2;" : "=r"(h01) : "f"(x.y), "f"(x.x));
    asm("cvt.rn.bf16x2.f32 %0, %1, %2;" : "=r"(h23) : "f"(x.w), "f"(x.z));

    const float hf0 = __uint_as_float(h01 << 16);
    const float hf1 = __uint_as_float(h01 & 0xffff0000u);
    const float hf2 = __uint_as_float(h23 << 16);
    const float hf3 = __uint_as_float(h23 & 0xffff0000u);

    uint32_t l01, l23;
    asm("cvt.rn.bf16x2.f32 %0, %1, %2;" : "=r"(l01) : "f"(x.y - hf1), "f"(x.x - hf0));
    asm("cvt.rn.bf16x2.f32 %0, %1, %2;" : "=r"(l23) : "f"(x.w - hf3), "f"(x.z - hf2));

    hi[i] = make_uint2(h01, h23);
    lo[i] = make_uint2(l01, l23);
}

// ---------------------------------------------------------------------------
// smem: per buffer Ah(16K) Al(16K) Bh(32K) Bl(32K) = 96KB, x2 = 192KB
// ---------------------------------------------------------------------------
#define AH_OFF 0
#define AL_OFF 16384
#define BH_OFF 32768
#define BL_OFF 65536
#define BUF_STRIDE 98304
#define SMEM_GEMM (2 * BUF_STRIDE)

// copy a (nrows x 64) bf16 tile, swizzled, 16B per cp.async
__device__ __forceinline__ void cpa_tile(uint32_t dst, const bf16* __restrict__ src,
                                         int ldk, int row0, int k0, int tid, int nrows)
{
    const int s  = tid & 7;
    const int r0 = tid >> 3;
    const char* g = (const char*)(src + (size_t)(row0 + r0) * ldk + k0) + s * 16;
    const uint32_t d0 = dst + r0 * 128 + ((s * 16) ^ ((r0 & 7) << 4));
    const size_t gs = (size_t)32 * ldk * 2;
#pragma unroll
    for (int i = 0; i < nrows / 32; i++)
        cp16(d0 + i * 32 * 128, g + i * gs);
}

__device__ __forceinline__ void issue_chunk(uint32_t buf,
    const bf16* Ah, const bf16* Al, const bf16* Bh, const bf16* Bl,
    int K, int m0, int n0, int k0, int tid)
{
    cpa_tile(buf + AH_OFF, Ah, K, m0, k0, tid, 128);
    cpa_tile(buf + AL_OFF, Al, K, m0, k0, tid, 128);
    cpa_tile(buf + BH_OFF, Bh, K, n0, k0, tid, 256);
    cpa_tile(buf + BL_OFF, Bl, K, n0, k0, tid, 256);
    CP_COMMIT();
}

// ---------------------------------------------------------------------------
// GEMM: C[M,N] = A[M,K] @ W[N,K]^T + bias (opt relu), hi/lo bf16 operands.
// ---------------------------------------------------------------------------
__global__ __launch_bounds__(256, 1)
void gemm_mma(const bf16* __restrict__ Ah, const bf16* __restrict__ Al,
              const bf16* __restrict__ Bh, const bf16* __restrict__ Bl,
              const float* __restrict__ bias, float* __restrict__ C,
              int M, int N, int K, int relu)
{
    extern __shared__ char smem[];
    const uint32_t sb = smem_u32(smem);

    const int tid = threadIdx.x;
    const int l   = tid & 31;
    const int w   = tid >> 5;
    const int mw  = w >> 2;
    const int nw  = w & 3;
    const int m0  = blockIdx.y * 128;
    const int n0  = blockIdx.x * 256;

    const uint32_t swz  = (uint32_t)((l & 7) << 4);
    const uint32_t ak   = (uint32_t)((l >> 4) << 4);
    const uint32_t bk   = (uint32_t)(((l >> 3) & 1) << 4);
    const uint32_t rowA = (uint32_t)((mw * 64 + (l & 15)) * 128);
    const uint32_t rowB = (uint32_t)((nw * 64 + ((l >> 4) << 3) + (l & 7)) * 128);

    float acc[4][8][4];
#pragma unroll
    for (int i = 0; i < 4; i++)
#pragma unroll
        for (int j = 0; j < 8; j++)
#pragma unroll
            for (int q = 0; q < 4; q++) acc[i][j][q] = 0.f;

    const int NC = K >> 6;

    issue_chunk(sb, Ah, Al, Bh, Bl, K, m0, n0, 0, tid);

    for (int c = 0; c < NC; c++) {
        const int b = c & 1;
        const uint32_t bufb = sb + b * BUF_STRIDE;

        CP_WAIT0();
        __syncthreads();

        if (c + 1 < NC)
            issue_chunk(sb + (b ^ 1) * BUF_STRIDE, Ah, Al, Bh, Bl, K, m0, n0, (c + 1) << 6, tid);

#pragma unroll
        for (int kk = 0; kk < 4; kk++) {
            const uint32_t kbB = ((uint32_t)(kk * 32) | bk) ^ swz;
            const uint32_t kbA = ((uint32_t)(kk * 32) | ak) ^ swz;

            uint32_t bh[16], bl[16];
            const uint32_t bB = bufb + BH_OFF + rowB + kbB;
#pragma unroll
            for (int j = 0; j < 4; j++) {
                ldsm4(bh + 4 * j, bB + j * 2048);
                ldsm4(bl + 4 * j, bB + j * 2048 + (BL_OFF - BH_OFF));
            }

            const uint32_t aB = bufb + AH_OFF + rowA + kbA;
#pragma unroll
            for (int mt = 0; mt < 4; mt++) {
                uint32_t ah[4], al[4];
                ldsm4(ah, aB + mt * 2048);
                ldsm4(al, aB + mt * 2048 + (AL_OFF - AH_OFF));
#pragma unroll
                for (int nt = 0; nt < 8; nt++) mma16816(acc[mt][nt], ah, bh + nt * 2);
#pragma unroll
                for (int nt = 0; nt < 8; nt++) mma16816(acc[mt][nt], ah, bl + nt * 2);
#pragma unroll
                for (int nt = 0; nt < 8; nt++) mma16816(acc[mt][nt], al, bh + nt * 2);
            }
        }
        __syncthreads();
    }

    const int row_base = m0 + mw * 64 + (l >> 2);
    const int col_base = n0 + nw * 64 + 2 * (l & 3);
#pragma unroll
    for (int mt = 0; mt < 4; mt++) {
        const int row = row_base + mt * 16;
#pragma unroll
        for (int nt = 0; nt < 8; nt++) {
            const int col = col_base + nt * 8;
            const float2 bv = *(const float2*)(bias + col);
            float2 r0, r1;
            r0.x = acc[mt][nt][0] + bv.x;  r0.y = acc[mt][nt][1] + bv.y;
            r1.x = acc[mt][nt][2] + bv.x;  r1.y = acc[mt][nt][3] + bv.y;
            if (relu) {
                r0.x = fmaxf(r0.x, 0.f); r0.y = fmaxf(r0.y, 0.f);
                r1.x = fmaxf(r1.x, 0.f); r1.y = fmaxf(r1.y, 0.f);
            }
            *(float2*)(C + (size_t)row * N + col)       = r0;
            *(float2*)(C + (size_t)(row + 8) * N + col) = r1;
        }
    }
}

// ---------------------------------------------------------------------------
// Attention: one block per query row m, warp = head. S=8, dh=64, scale=0.125
// ---------------------------------------------------------------------------
__global__ __launch_bounds__(256)
void attn_kernel(const float* __restrict__ Qp, const float* __restrict__ Kp,
                 const float* __restrict__ Vp, float* __restrict__ out)
{
    const int m = blockIdx.x;
    const int w = threadIdx.x >> 5;
    const int l = threadIdx.x & 31;

    const size_t qoff = (size_t)m * Hdim + w * 64;
    const float q0 = Qp[qoff + l];
    const float q1 = Qp[qoff + l + 32];

    float s[8];
#pragma unroll
    for (int c = 0; c < 8; c++) {
        const float* k = Kp + ((size_t)m * 8 + c) * Hdim + w * 64;
        float p = q0 * k[l] + q1 * k[l + 32];
#pragma unroll
        for (int o = 16; o > 0; o >>= 1)
            p += __shfl_xor_sync(0xffffffffu, p, o);
        s[c] = p * 0.125f;
    }

    float mx = s[0];
#pragma unroll
    for (int c = 1; c < 8; c++) mx = fmaxf(mx, s[c]);
    float sum = 0.f;
#pragma unroll
    for (int c = 0; c < 8; c++) { s[c] = __expf(s[c] - mx); sum += s[c]; }
    const float inv = 1.f / sum;

    float o0 = 0.f, o1 = 0.f;
#pragma unroll
    for (int c = 0; c < 8; c++) {
        const float* v = Vp + ((size_t)m * 8 + c) * Hdim + w * 64;
        const float p = s[c] * inv;
        o0 += p * v[l];
        o1 += p * v[l + 32];
    }
    out[qoff + l]      = o0;
    out[qoff + l + 32] = o1;
}

// ---------------------------------------------------------------------------
// LayerNorm(x + r) over H=512, one block (256 threads) per row.
// ---------------------------------------------------------------------------
__global__ __launch_bounds__(256)
void ln_residual_kernel(const float* __restrict__ x, const float* __restrict__ r,
                        const float* __restrict__ g, const float* __restrict__ bt,
                        float* __restrict__ out)
{
    __shared__ float red[16];
    const int m = blockIdx.x;
    const int t = threadIdx.x;
    const int l = t & 31;
    const int w = t >> 5;
    const size_t base = (size_t)m * Hdim;

    const float s0 = x[base + t]       + r[base + t];
    const float s1 = x[base + t + 256] + r[base + t + 256];

    float v = s0 + s1;
#pragma unroll
    for (int o = 16; o > 0; o >>= 1) v += __shfl_xor_sync(0xffffffffu, v, o);
    if (l == 0) red[w] = v;
    __syncthreads();
    float mean = 0.f;
#pragma unroll
    for (int i = 0; i < 8; i++) mean += red[i];
    mean *= (1.f / 512.f);

    const float d0 = s0 - mean, d1 = s1 - mean;
    float vv = d0 * d0 + d1 * d1;
#pragma unroll
    for (int o = 16; o > 0; o >>= 1) vv += __shfl_xor_sync(0xffffffffu, vv, o);
    if (l == 0) red[8 + w] = vv;
    __syncthreads();
    float var = 0.f;
#pragma unroll
    for (int i = 0; i < 8; i++) var += red[8 + i];
    var *= (1.f / 512.f);
    const float rstd = rsqrtf(var + 1e-5f);

    out[base + t]       = d0 * rstd * g[t]       + bt[t];
    out[base + t + 256] = d1 * rstd * g[t + 256] + bt[t + 256];
}

// ---------------------------------------------------------------------------
extern "C" void kernel_launch(void* const* d_in, const int* in_sizes, int n_in,
                              void* d_out, int out_size)
{
    (void)in_sizes; (void)n_in; (void)out_size;
    const float* query = (const float*)d_in[0];
    const float* key   = (const float*)d_in[1];
    const float* value = (const float*)d_in[2];
    const float* Wq    = (const float*)d_in[3];
    const float* bq    = (const float*)d_in[4];
    const float* Wk    = (const float*)d_in[5];
    const float* bk    = (const float*)d_in[6];
    const float* Wv    = (const float*)d_in[7];
    const float* bv    = (const float*)d_in[8];
    const float* Wo    = (const float*)d_in[9];
    const float* bo    = (const float*)d_in[10];
    const float* ln1g  = (const float*)d_in[11];
    const float* ln1b  = (const float*)d_in[12];
    const float* W1    = (const float*)d_in[13];
    const float* b1    = (const float*)d_in[14];
    const float* W2    = (const float*)d_in[15];
    const float* b2    = (const float*)d_in[16];
    const float* ln2g  = (const float*)d_in[17];
    const float* ln2b  = (const float*)d_in[18];
    float* out = (float*)d_out;

    float *Qp, *Kp, *Vp, *att, *x, *h1, *f1;
    cudaGetSymbolAddress((void**)&Qp,  g_Qp);
    cudaGetSymbolAddress((void**)&Kp,  g_Kp);
    cudaGetSymbolAddress((void**)&Vp,  g_Vp);
    cudaGetSymbolAddress((void**)&att, g_att);
    cudaGetSymbolAddress((void**)&x,   g_x);
    cudaGetSymbolAddress((void**)&h1,  g_h1);
    cudaGetSymbolAddress((void**)&f1,  g_f1);

    bf16 *qh,*ql,*kh,*kl,*vh,*vl,*ath,*atl,*h1h,*h1l,*f1h,*f1l;
    bf16 *wqh,*wql,*wkh,*wkl,*wvh,*wvl,*woh,*wol,*w1h,*w1l,*w2h,*w2l;
    cudaGetSymbolAddress((void**)&qh,  g_q_h);  cudaGetSymbolAddress((void**)&ql,  g_q_l);
    cudaGetSymbolAddress((void**)&kh,  g_k_h);  cudaGetSymbolAddress((void**)&kl,  g_k_l);
    cudaGetSymbolAddress((void**)&vh,  g_v_h);  cudaGetSymbolAddress((void**)&vl,  g_v_l);
    cudaGetSymbolAddress((void**)&ath, g_at_h); cudaGetSymbolAddress((void**)&atl, g_at_l);
    cudaGetSymbolAddress((void**)&h1h, g_h1_h); cudaGetSymbolAddress((void**)&h1l, g_h1_l);
    cudaGetSymbolAddress((void**)&f1h, g_f1_h); cudaGetSymbolAddress((void**)&f1l, g_f1_l);
    cudaGetSymbolAddress((void**)&wqh, g_wq_h); cudaGetSymbolAddress((void**)&wql, g_wq_l);
    cudaGetSymbolAddress((void**)&wkh, g_wk_h); cudaGetSymbolAddress((void**)&wkl, g_wk_l);
    cudaGetSymbolAddress((void**)&wvh, g_wv_h); cudaGetSymbolAddress((void**)&wvl, g_wv_l);
    cudaGetSymbolAddress((void**)&woh, g_wo_h); cudaGetSymbolAddress((void**)&wol, g_wo_l);
    cudaGetSymbolAddress((void**)&w1h, g_w1_h); cudaGetSymbolAddress((void**)&w1l, g_w1_l);
    cudaGetSymbolAddress((void**)&w2h, g_w2_h); cudaGetSymbolAddress((void**)&w2l, g_w2_l);

    cudaFuncSetAttribute(gemm_mma, cudaFuncAttributeMaxDynamicSharedMemorySize, SMEM_GEMM);

    #define CVT(src, hi, lo, n) \
        cvt_hl<<<((n)/4 + 255)/256, 256>>>((const float4*)(src), (uint2*)(hi), (uint2*)(lo), (n)/4)

    // weights
    CVT(Wq, wqh, wql, Hdim*Hdim);
    CVT(Wk, wkh, wkl, Hdim*Hdim);
    CVT(Wv, wvh, wvl, Hdim*Hdim);
    CVT(Wo, woh, wol, Hdim*Hdim);
    CVT(W1, w1h, w1l, HF*Hdim);
    CVT(W2, w2h, w2l, Hdim*HF);

    // Q/K/V projections
    CVT(query, qh, ql, M_Q*Hdim);
    CVT(key,   kh, kl, M_KV*Hdim);
    CVT(value, vh, vl, M_KV*Hdim);
    gemm_mma<<<dim3(Hdim/256, M_Q /128), 256, SMEM_GEMM>>>(qh, ql, wqh, wql, bq, Qp, M_Q,  Hdim, Hdim, 0);
    gemm_mma<<<dim3(Hdim/256, M_KV/128), 256, SMEM_GEMM>>>(kh, kl, wkh, wkl, bk, Kp, M_KV, Hdim, Hdim, 0);
    gemm_mma<<<dim3(Hdim/256, M_KV/128), 256, SMEM_GEMM>>>(vh, vl, wvh, wvl, bv, Vp, M_KV, Hdim, Hdim, 0);

    // attention
    attn_kernel<<<M_Q, 256>>>(Qp, Kp, Vp, att);

    // O projection + residual + LN1
    CVT(att, ath, atl, M_Q*Hdim);
    gemm_mma<<<dim3(Hdim/256, M_Q/128), 256, SMEM_GEMM>>>(ath, atl, woh, wol, bo, x, M_Q, Hdim, Hdim, 0);
    ln_residual_kernel<<<M_Q, 256>>>(x, query, ln1g, ln1b, h1);

    // FFN + residual + LN2
    CVT(h1, h1h, h1l, M_Q*Hdim);
    gemm_mma<<<dim3(HF/256, M_Q/128), 256, SMEM_GEMM>>>(h1h, h1l, w1h, w1l, b1, f1, M_Q, HF, Hdim, 1);
    CVT(f1, f1h, f1l, M_Q*HF);
    gemm_mma<<<dim3(Hdim/256, M_Q/128), 256, SMEM_GEMM>>>(f1h, f1l, w2h, w2l, b2, x, M_Q, Hdim, HF, 0);
    ln_residual_kernel<<<M_Q, 256>>>(x, h1, ln2g, ln2b, out);
}

// round 6
// speedup vs baseline: 1.6252x; 1.3234x over previous
#include <cuda_runtime.h>
#include <cuda_fp16.h>
#include <cstdint>

// ---------------------------------------------------------------------------
// AttentionEncoderLayer: B=4, C=8, F=2048, H=512, NH=8, dh=64, Hf=1024
//   M = F*B = 8192 query rows; key/value flat [65536,512];
//   query row m attends KV rows [8m, 8m+8).
// GEMMs: 2-pass split-fp16 HMMA:  A = Ah + Al (fp16 each, 22 bits),
//   B = Bh (fp16);  D = Ah*Bh + Al*Bh  (fp32 accum).
//   Error ~ 0.29*2^-11 per GEMM from B rounding -> ~3e-4 end to end.
// Tile BM=128 x BN=256 x BK=64, 8 warps (64x64 each), 3-stage cp.async.
// ---------------------------------------------------------------------------

#define M_Q   8192
#define M_KV  65536
#define Hdim  512
#define HF    1024

typedef __half f16;

// fp32 intermediates
__device__ float g_Qp [M_Q  * Hdim];
__device__ float g_Kp [M_KV * Hdim];
__device__ float g_Vp [M_KV * Hdim];
__device__ float g_x  [M_Q  * Hdim];
__device__ float g_h1 [M_Q  * Hdim];

// fp16 hi/lo planes (GEMM A operands) and hi-only weights (B operands)
__device__ f16 g_q_h [M_Q  * Hdim];  __device__ f16 g_q_l [M_Q  * Hdim];
__device__ f16 g_k_h [M_KV * Hdim];  __device__ f16 g_k_l [M_KV * Hdim];
__device__ f16 g_v_h [M_KV * Hdim];  __device__ f16 g_v_l [M_KV * Hdim];
__device__ f16 g_at_h[M_Q  * Hdim];  __device__ f16 g_at_l[M_Q  * Hdim];
__device__ f16 g_h1_h[M_Q  * Hdim];  __device__ f16 g_h1_l[M_Q  * Hdim];
__device__ f16 g_f1_h[M_Q  * HF  ];  __device__ f16 g_f1_l[M_Q  * HF  ];
__device__ f16 g_wq_h[Hdim * Hdim];
__device__ f16 g_wk_h[Hdim * Hdim];
__device__ f16 g_wv_h[Hdim * Hdim];
__device__ f16 g_wo_h[Hdim * Hdim];
__device__ f16 g_w1_h[HF * Hdim];
__device__ f16 g_w2_h[Hdim * HF];

// ---------------- helpers ----------------
__device__ __forceinline__ uint32_t smem_u32(const void* p) {
    uint32_t a;
    asm("{ .reg .u64 t; cvta.to.shared.u64 t, %1; cvt.u32.u64 %0, t; }" : "=r"(a) : "l"(p));
    return a;
}
__device__ __forceinline__ void ldsm4(uint32_t* r, uint32_t addr) {
    asm volatile("ldmatrix.sync.aligned.m8n8.x4.shared.b16 {%0,%1,%2,%3}, [%4];"
                 : "=r"(r[0]), "=r"(r[1]), "=r"(r[2]), "=r"(r[3]) : "r"(addr));
}
__device__ __forceinline__ void mma16816(float* d, const uint32_t* a, const uint32_t* b) {
    asm volatile("mma.sync.aligned.m16n8k16.row.col.f32.f16.f16.f32 "
                 "{%0,%1,%2,%3}, {%4,%5,%6,%7}, {%8,%9}, {%0,%1,%2,%3};"
                 : "+f"(d[0]), "+f"(d[1]), "+f"(d[2]), "+f"(d[3])
                 : "r"(a[0]), "r"(a[1]), "r"(a[2]), "r"(a[3]), "r"(b[0]), "r"(b[1]));
}
__device__ __forceinline__ void cp16(uint32_t dst, const void* src) {
    asm volatile("cp.async.cg.shared.global [%0], [%1], 16;" :: "r"(dst), "l"(src));
}
#define CP_COMMIT() asm volatile("cp.async.commit_group;" ::: "memory")
#define CP_WAIT1()  asm volatile("cp.async.wait_group 1;" ::: "memory")
#define CP_WAIT0()  asm volatile("cp.async.wait_group 0;" ::: "memory")

// ---------------------------------------------------------------------------
// prepass: fp32 -> fp16 hi (+ lo).  n4 = elements/4.
// ---------------------------------------------------------------------------
__global__ __launch_bounds__(256)
void cvt_hl16(const float4* __restrict__ src, uint2* __restrict__ hi,
              uint2* __restrict__ lo, int n4)
{
    const int i = blockIdx.x * 256 + threadIdx.x;
    if (i >= n4) return;
    const float4 x = src[i];
    __half2 h01 = __floats2half2_rn(x.x, x.y);
    __half2 h23 = __floats2half2_rn(x.z, x.w);
    float2 f01 = __half22float2(h01);
    float2 f23 = __half22float2(h23);
    __half2 l01 = __floats2half2_rn(x.x - f01.x, x.y - f01.y);
    __half2 l23 = __floats2half2_rn(x.z - f23.x, x.w - f23.y);
    hi[i] = make_uint2(*(uint32_t*)&h01, *(uint32_t*)&h23);
    lo[i] = make_uint2(*(uint32_t*)&l01, *(uint32_t*)&l23);
}

__global__ __launch_bounds__(256)
void cvt_h16(const float4* __restrict__ src, uint2* __restrict__ hi, int n4)
{
    const int i = blockIdx.x * 256 + threadIdx.x;
    if (i >= n4) return;
    const float4 x = src[i];
    __half2 h01 = __floats2half2_rn(x.x, x.y);
    __half2 h23 = __floats2half2_rn(x.z, x.w);
    hi[i] = make_uint2(*(uint32_t*)&h01, *(uint32_t*)&h23);
}

// ---------------------------------------------------------------------------
// smem: per buffer Ah(16K) Al(16K) Bh(32K) = 64KB, x3 stages = 192KB
// ---------------------------------------------------------------------------
#define AH_OFF 0
#define AL_OFF 16384
#define BH_OFF 32768
#define BUF_STRIDE 65536
#define SMEM_GEMM (3 * BUF_STRIDE)

// copy a (nrows x 64) fp16 tile, swizzled, 16B per cp.async
__device__ __forceinline__ void cpa_tile(uint32_t dst, const f16* __restrict__ src,
                                         int ldk, int row0, int k0, int tid, int nrows)
{
    const int s  = tid & 7;
    const int r0 = tid >> 3;
    const char* g = (const char*)(src + (size_t)(row0 + r0) * ldk + k0) + s * 16;
    const uint32_t d0 = dst + r0 * 128 + ((s * 16) ^ ((r0 & 7) << 4));
    const size_t gs = (size_t)32 * ldk * 2;
#pragma unroll
    for (int i = 0; i < nrows / 32; i++)
        cp16(d0 + i * 32 * 128, g + i * gs);
}

__device__ __forceinline__ void issue_chunk(uint32_t buf,
    const f16* Ah, const f16* Al, const f16* Bh,
    int K, int m0, int n0, int k0, int tid)
{
    cpa_tile(buf + AH_OFF, Ah, K, m0, k0, tid, 128);
    cpa_tile(buf + AL_OFF, Al, K, m0, k0, tid, 128);
    cpa_tile(buf + BH_OFF, Bh, K, n0, k0, tid, 256);
    CP_COMMIT();
}

// ---------------------------------------------------------------------------
// GEMM: D[M,N] = A[M,K] @ W[N,K]^T + bias (opt relu)
//   outputs: fp32 C (if non-null) and/or fp16 hi/lo planes (if non-null)
// ---------------------------------------------------------------------------
__global__ __launch_bounds__(256, 1)
void gemm_mma(const f16* __restrict__ Ah, const f16* __restrict__ Al,
              const f16* __restrict__ Bh, const float* __restrict__ bias,
              float* __restrict__ C, f16* __restrict__ Ch, f16* __restrict__ Cl,
              int M, int N, int K, int relu)
{
    extern __shared__ char smem[];
    const uint32_t sb = smem_u32(smem);

    const int tid = threadIdx.x;
    const int l   = tid & 31;
    const int w   = tid >> 5;
    const int mw  = w >> 2;
    const int nw  = w & 3;
    const int m0  = blockIdx.y * 128;
    const int n0  = blockIdx.x * 256;

    const uint32_t swz  = (uint32_t)((l & 7) << 4);
    const uint32_t ak   = (uint32_t)((l >> 4) << 4);
    const uint32_t bk   = (uint32_t)(((l >> 3) & 1) << 4);
    const uint32_t rowA = (uint32_t)((mw * 64 + (l & 15)) * 128);
    const uint32_t rowB = (uint32_t)((nw * 64 + ((l >> 4) << 3) + (l & 7)) * 128);

    float acc[4][8][4];
#pragma unroll
    for (int i = 0; i < 4; i++)
#pragma unroll
        for (int j = 0; j < 8; j++)
#pragma unroll
            for (int q = 0; q < 4; q++) acc[i][j][q] = 0.f;

    const int NC = K >> 6;

    issue_chunk(sb,              Ah, Al, Bh, K, m0, n0, 0,  tid);
    if (NC > 1)
        issue_chunk(sb + BUF_STRIDE, Ah, Al, Bh, K, m0, n0, 64, tid);

    for (int c = 0; c < NC; c++) {
        const uint32_t bufb = sb + (c % 3) * BUF_STRIDE;

        if (c + 1 < NC) CP_WAIT1(); else CP_WAIT0();
        __syncthreads();

        if (c + 2 < NC)
            issue_chunk(sb + ((c + 2) % 3) * BUF_STRIDE, Ah, Al, Bh, K, m0, n0, (c + 2) << 6, tid);

#pragma unroll
        for (int kk = 0; kk < 4; kk++) {
            const uint32_t kbB = ((uint32_t)(kk * 32) | bk) ^ swz;
            const uint32_t kbA = ((uint32_t)(kk * 32) | ak) ^ swz;

            uint32_t bh[16];
            const uint32_t bB = bufb + BH_OFF + rowB + kbB;
#pragma unroll
            for (int j = 0; j < 4; j++)
                ldsm4(bh + 4 * j, bB + j * 2048);

            const uint32_t aB = bufb + AH_OFF + rowA + kbA;
#pragma unroll
            for (int mt = 0; mt < 4; mt++) {
                uint32_t ah[4], al[4];
                ldsm4(ah, aB + mt * 2048);
                ldsm4(al, aB + mt * 2048 + (AL_OFF - AH_OFF));
#pragma unroll
                for (int nt = 0; nt < 8; nt++) mma16816(acc[mt][nt], ah, bh + nt * 2);
#pragma unroll
                for (int nt = 0; nt < 8; nt++) mma16816(acc[mt][nt], al, bh + nt * 2);
            }
        }
    }

    // epilogue
    const int row_base = m0 + mw * 64 + (l >> 2);
    const int col_base = n0 + nw * 64 + 2 * (l & 3);
#pragma unroll
    for (int mt = 0; mt < 4; mt++) {
        const int row = row_base + mt * 16;
#pragma unroll
        for (int nt = 0; nt < 8; nt++) {
            const int col = col_base + nt * 8;
            const float2 bv = *(const float2*)(bias + col);
            float r[4];
            r[0] = acc[mt][nt][0] + bv.x;  r[1] = acc[mt][nt][1] + bv.y;
            r[2] = acc[mt][nt][2] + bv.x;  r[3] = acc[mt][nt][3] + bv.y;
            if (relu) {
#pragma unroll
                for (int q = 0; q < 4; q++) r[q] = fmaxf(r[q], 0.f);
            }
            if (C) {
                *(float2*)(C + (size_t)row * N + col)       = make_float2(r[0], r[1]);
                *(float2*)(C + (size_t)(row + 8) * N + col) = make_float2(r[2], r[3]);
            }
            if (Ch) {
                __half2 h0 = __floats2half2_rn(r[0], r[1]);
                __half2 h1 = __floats2half2_rn(r[2], r[3]);
                float2 f0 = __half22float2(h0);
                float2 f1 = __half22float2(h1);
                __half2 l0 = __floats2half2_rn(r[0] - f0.x, r[1] - f0.y);
                __half2 l1 = __floats2half2_rn(r[2] - f1.x, r[3] - f1.y);
                *(__half2*)(Ch + (size_t)row * N + col)       = h0;
                *(__half2*)(Ch + (size_t)(row + 8) * N + col) = h1;
                *(__half2*)(Cl + (size_t)row * N + col)       = l0;
                *(__half2*)(Cl + (size_t)(row + 8) * N + col) = l1;
            }
        }
    }
}

// ---------------------------------------------------------------------------
// Attention: one block per query row m, warp = head. S=8, dh=64, scale=0.125
// Writes fp16 hi/lo planes directly (feeds O-projection).
// ---------------------------------------------------------------------------
__global__ __launch_bounds__(256)
void attn_kernel(const float* __restrict__ Qp, const float* __restrict__ Kp,
                 const float* __restrict__ Vp,
                 f16* __restrict__ oh, f16* __restrict__ ol)
{
    const int m = blockIdx.x;
    const int w = threadIdx.x >> 5;
    const int l = threadIdx.x & 31;

    const size_t qoff = (size_t)m * Hdim + w * 64;
    const float q0 = Qp[qoff + l];
    const float q1 = Qp[qoff + l + 32];

    float s[8];
#pragma unroll
    for (int c = 0; c < 8; c++) {
        const float* k = Kp + ((size_t)m * 8 + c) * Hdim + w * 64;
        float p = q0 * k[l] + q1 * k[l + 32];
#pragma unroll
        for (int o = 16; o > 0; o >>= 1)
            p += __shfl_xor_sync(0xffffffffu, p, o);
        s[c] = p * 0.125f;
    }

    float mx = s[0];
#pragma unroll
    for (int c = 1; c < 8; c++) mx = fmaxf(mx, s[c]);
    float sum = 0.f;
#pragma unroll
    for (int c = 0; c < 8; c++) { s[c] = __expf(s[c] - mx); sum += s[c]; }
    const float inv = 1.f / sum;

    float o0 = 0.f, o1 = 0.f;
#pragma unroll
    for (int c = 0; c < 8; c++) {
        const float* v = Vp + ((size_t)m * 8 + c) * Hdim + w * 64;
        const float p = s[c] * inv;
        o0 += p * v[l];
        o1 += p * v[l + 32];
    }
    const f16 h0 = __float2half_rn(o0);
    const f16 h1 = __float2half_rn(o1);
    oh[qoff + l]      = h0;
    oh[qoff + l + 32] = h1;
    ol[qoff + l]      = __float2half_rn(o0 - __half2float(h0));
    ol[qoff + l + 32] = __float2half_rn(o1 - __half2float(h1));
}

// ---------------------------------------------------------------------------
// LayerNorm(x + r) over H=512, one block (256 threads) per row.
// Optionally also emits fp16 hi/lo planes of the result.
// ---------------------------------------------------------------------------
__global__ __launch_bounds__(256)
void ln_residual_kernel(const float* __restrict__ x, const float* __restrict__ r,
                        const float* __restrict__ g, const float* __restrict__ bt,
                        float* __restrict__ out,
                        f16* __restrict__ oh, f16* __restrict__ ol)
{
    __shared__ float red[16];
    const int m = blockIdx.x;
    const int t = threadIdx.x;
    const int l = t & 31;
    const int w = t >> 5;
    const size_t base = (size_t)m * Hdim;

    const float s0 = x[base + t]       + r[base + t];
    const float s1 = x[base + t + 256] + r[base + t + 256];

    float v = s0 + s1;
#pragma unroll
    for (int o = 16; o > 0; o >>= 1) v += __shfl_xor_sync(0xffffffffu, v, o);
    if (l == 0) red[w] = v;
    __syncthreads();
    float mean = 0.f;
#pragma unroll
    for (int i = 0; i < 8; i++) mean += red[i];
    mean *= (1.f / 512.f);

    const float d0 = s0 - mean, d1 = s1 - mean;
    float vv = d0 * d0 + d1 * d1;
#pragma unroll
    for (int o = 16; o > 0; o >>= 1) vv += __shfl_xor_sync(0xffffffffu, vv, o);
    if (l == 0) red[8 + w] = vv;
    __syncthreads();
    float var = 0.f;
#pragma unroll
    for (int i = 0; i < 8; i++) var += red[8 + i];
    var *= (1.f / 512.f);
    const float rstd = rsqrtf(var + 1e-5f);

    const float y0 = d0 * rstd * g[t]       + bt[t];
    const float y1 = d1 * rstd * g[t + 256] + bt[t + 256];
    out[base + t]       = y0;
    out[base + t + 256] = y1;
    if (oh) {
        const f16 h0 = __float2half_rn(y0);
        const f16 h1 = __float2half_rn(y1);
        oh[base + t]       = h0;
        oh[base + t + 256] = h1;
        ol[base + t]       = __float2half_rn(y0 - __half2float(h0));
        ol[base + t + 256] = __float2half_rn(y1 - __half2float(h1));
    }
}

// ---------------------------------------------------------------------------
extern "C" void kernel_launch(void* const* d_in, const int* in_sizes, int n_in,
                              void* d_out, int out_size)
{
    (void)in_sizes; (void)n_in; (void)out_size;
    const float* query = (const float*)d_in[0];
    const float* key   = (const float*)d_in[1];
    const float* value = (const float*)d_in[2];
    const float* Wq    = (const float*)d_in[3];
    const float* bq    = (const float*)d_in[4];
    const float* Wk    = (const float*)d_in[5];
    const float* bk    = (const float*)d_in[6];
    const float* Wv    = (const float*)d_in[7];
    const float* bv    = (const float*)d_in[8];
    const float* Wo    = (const float*)d_in[9];
    const float* bo    = (const float*)d_in[10];
    const float* ln1g  = (const float*)d_in[11];
    const float* ln1b  = (const float*)d_in[12];
    const float* W1    = (const float*)d_in[13];
    const float* b1    = (const float*)d_in[14];
    const float* W2    = (const float*)d_in[15];
    const float* b2    = (const float*)d_in[16];
    const float* ln2g  = (const float*)d_in[17];
    const float* ln2b  = (const float*)d_in[18];
    float* out = (float*)d_out;

    float *Qp, *Kp, *Vp, *x, *h1;
    cudaGetSymbolAddress((void**)&Qp, g_Qp);
    cudaGetSymbolAddress((void**)&Kp, g_Kp);
    cudaGetSymbolAddress((void**)&Vp, g_Vp);
    cudaGetSymbolAddress((void**)&x,  g_x);
    cudaGetSymbolAddress((void**)&h1, g_h1);

    f16 *qh,*ql,*kh,*kl,*vh,*vl,*ath,*atl,*h1h,*h1l,*f1h,*f1l;
    f16 *wqh,*wkh,*wvh,*woh,*w1h,*w2h;
    cudaGetSymbolAddress((void**)&qh,  g_q_h);  cudaGetSymbolAddress((void**)&ql,  g_q_l);
    cudaGetSymbolAddress((void**)&kh,  g_k_h);  cudaGetSymbolAddress((void**)&kl,  g_k_l);
    cudaGetSymbolAddress((void**)&vh,  g_v_h);  cudaGetSymbolAddress((void**)&vl,  g_v_l);
    cudaGetSymbolAddress((void**)&ath, g_at_h); cudaGetSymbolAddress((void**)&atl, g_at_l);
    cudaGetSymbolAddress((void**)&h1h, g_h1_h); cudaGetSymbolAddress((void**)&h1l, g_h1_l);
    cudaGetSymbolAddress((void**)&f1h, g_f1_h); cudaGetSymbolAddress((void**)&f1l, g_f1_l);
    cudaGetSymbolAddress((void**)&wqh, g_wq_h);
    cudaGetSymbolAddress((void**)&wkh, g_wk_h);
    cudaGetSymbolAddress((void**)&wvh, g_wv_h);
    cudaGetSymbolAddress((void**)&woh, g_wo_h);
    cudaGetSymbolAddress((void**)&w1h, g_w1_h);
    cudaGetSymbolAddress((void**)&w2h, g_w2_h);

    cudaFuncSetAttribute(gemm_mma, cudaFuncAttributeMaxDynamicSharedMemorySize, SMEM_GEMM);

    #define CVT2(src, hi, lo, n) \
        cvt_hl16<<<((n)/4 + 255)/256, 256>>>((const float4*)(src), (uint2*)(hi), (uint2*)(lo), (n)/4)
    #define CVT1(src, hi, n) \
        cvt_h16<<<((n)/4 + 255)/256, 256>>>((const float4*)(src), (uint2*)(hi), (n)/4)

    // weights (hi only)
    CVT1(Wq, wqh, Hdim*Hdim);
    CVT1(Wk, wkh, Hdim*Hdim);
    CVT1(Wv, wvh, Hdim*Hdim);
    CVT1(Wo, woh, Hdim*Hdim);
    CVT1(W1, w1h, HF*Hdim);
    CVT1(W2, w2h, Hdim*HF);

    // activations (hi + lo)
    CVT2(query, qh, ql, M_Q*Hdim);
    CVT2(key,   kh, kl, M_KV*Hdim);
    CVT2(value, vh, vl, M_KV*Hdim);

    // Q/K/V projections (fp32 out, feed attention)
    gemm_mma<<<dim3(Hdim/256, M_Q /128), 256, SMEM_GEMM>>>(qh, ql, wqh, bq, Qp, 0, 0, M_Q,  Hdim, Hdim, 0);
    gemm_mma<<<dim3(Hdim/256, M_KV/128), 256, SMEM_GEMM>>>(kh, kl, wkh, bk, Kp, 0, 0, M_KV, Hdim, Hdim, 0);
    gemm_mma<<<dim3(Hdim/256, M_KV/128), 256, SMEM_GEMM>>>(vh, vl, wvh, bv, Vp, 0, 0, M_KV, Hdim, Hdim, 0);

    // attention -> fp16 hi/lo planes
    attn_kernel<<<M_Q, 256>>>(Qp, Kp, Vp, ath, atl);

    // O projection (fp32) + residual + LN1 (fp32 + hi/lo)
    gemm_mma<<<dim3(Hdim/256, M_Q/128), 256, SMEM_GEMM>>>(ath, atl, woh, bo, x, 0, 0, M_Q, Hdim, Hdim, 0);
    ln_residual_kernel<<<M_Q, 256>>>(x, query, ln1g, ln1b, h1, h1h, h1l);

    // FFN1 (relu, fp16 hi/lo only) -> FFN2 (fp32) -> LN2 (final out)
    gemm_mma<<<dim3(HF/256, M_Q/128), 256, SMEM_GEMM>>>(h1h, h1l, w1h, b1, 0, f1h, f1l, M_Q, HF, Hdim, 1);
    gemm_mma<<<dim3(Hdim/256, M_Q/128), 256, SMEM_GEMM>>>(f1h, f1l, w2h, b2, x, 0, 0, M_Q, Hdim, HF, 0);
    ln_residual_kernel<<<M_Q, 256>>>(x, h1, ln2g, ln2b, out, 0, 0);
}

// round 7
// speedup vs baseline: 2.3249x; 1.4306x over previous
#include <cuda_runtime.h>
#include <cuda_fp16.h>
#include <cstdint>

// ---------------------------------------------------------------------------
// AttentionEncoderLayer: B=4, C=8, F=2048, H=512, NH=8, dh=64, Hf=1024
//   M = F*B = 8192 query rows; key/value flat [65536,512];
//   query row m attends KV rows [8m, 8m+8).
// GEMMs: 1-pass fp16 HMMA (fp32 accum). Measured: legacy-HMMA pipe floor
// ~12 cyc per m16n8k16 per SMSP is the binder, so minimize MMA count.
// Residual spine (query, x, h1) stays fp32; LN in fp32.
// Tile BM=128 x BN=256 x BK=64, 8 warps (64x64 each), 3-stage cp.async.
// ---------------------------------------------------------------------------

#define M_Q   8192
#define M_KV  65536
#define Hdim  512
#define HF    1024

typedef __half f16;

// fp32 intermediates (residual spine)
__device__ float g_x  [M_Q * Hdim];
__device__ float g_h1 [M_Q * Hdim];

// fp16 activations / weights
__device__ f16 g_q16 [M_Q  * Hdim];
__device__ f16 g_k16 [M_KV * Hdim];
__device__ f16 g_v16 [M_KV * Hdim];
__device__ f16 g_Qp16[M_Q  * Hdim];
__device__ f16 g_Kp16[M_KV * Hdim];
__device__ f16 g_Vp16[M_KV * Hdim];
__device__ f16 g_at16[M_Q  * Hdim];
__device__ f16 g_h1h [M_Q  * Hdim];
__device__ f16 g_f1h [M_Q  * HF  ];
__device__ f16 g_wq16[Hdim * Hdim];
__device__ f16 g_wk16[Hdim * Hdim];
__device__ f16 g_wv16[Hdim * Hdim];
__device__ f16 g_wo16[Hdim * Hdim];
__device__ f16 g_w116[HF * Hdim];
__device__ f16 g_w216[Hdim * HF];

// ---------------- helpers ----------------
__device__ __forceinline__ uint32_t smem_u32(const void* p) {
    uint32_t a;
    asm("{ .reg .u64 t; cvta.to.shared.u64 t, %1; cvt.u32.u64 %0, t; }" : "=r"(a) : "l"(p));
    return a;
}
__device__ __forceinline__ void ldsm4(uint32_t* r, uint32_t addr) {
    asm volatile("ldmatrix.sync.aligned.m8n8.x4.shared.b16 {%0,%1,%2,%3}, [%4];"
                 : "=r"(r[0]), "=r"(r[1]), "=r"(r[2]), "=r"(r[3]) : "r"(addr));
}
__device__ __forceinline__ void mma16816(float* d, const uint32_t* a, const uint32_t* b) {
    asm volatile("mma.sync.aligned.m16n8k16.row.col.f32.f16.f16.f32 "
                 "{%0,%1,%2,%3}, {%4,%5,%6,%7}, {%8,%9}, {%0,%1,%2,%3};"
                 : "+f"(d[0]), "+f"(d[1]), "+f"(d[2]), "+f"(d[3])
                 : "r"(a[0]), "r"(a[1]), "r"(a[2]), "r"(a[3]), "r"(b[0]), "r"(b[1]));
}
__device__ __forceinline__ void cp16(uint32_t dst, const void* src) {
    asm volatile("cp.async.cg.shared.global [%0], [%1], 16;" :: "r"(dst), "l"(src));
}
#define CP_COMMIT() asm volatile("cp.async.commit_group;" ::: "memory")
#define CP_WAIT1()  asm volatile("cp.async.wait_group 1;" ::: "memory")
#define CP_WAIT0()  asm volatile("cp.async.wait_group 0;" ::: "memory")

// ---------------------------------------------------------------------------
// prepass: fp32 -> fp16.  n4 = elements/4.
// ---------------------------------------------------------------------------
__global__ __launch_bounds__(256)
void cvt_h16(const float4* __restrict__ src, uint2* __restrict__ hi, int n4)
{
    const int i = blockIdx.x * 256 + threadIdx.x;
    if (i >= n4) return;
    const float4 x = src[i];
    __half2 h01 = __floats2half2_rn(x.x, x.y);
    __half2 h23 = __floats2half2_rn(x.z, x.w);
    hi[i] = make_uint2(*(uint32_t*)&h01, *(uint32_t*)&h23);
}

// ---------------------------------------------------------------------------
// smem: per buffer A(16K) B(32K) = 48KB, x3 stages = 144KB
// ---------------------------------------------------------------------------
#define A_OFF 0
#define B_OFF 16384
#define BUF_STRIDE 49152
#define SMEM_GEMM (3 * BUF_STRIDE)

// copy a (nrows x 64) fp16 tile, swizzled, 16B per cp.async
__device__ __forceinline__ void cpa_tile(uint32_t dst, const f16* __restrict__ src,
                                         int ldk, int row0, int k0, int tid, int nrows)
{
    const int s  = tid & 7;
    const int r0 = tid >> 3;
    const char* g = (const char*)(src + (size_t)(row0 + r0) * ldk + k0) + s * 16;
    const uint32_t d0 = dst + r0 * 128 + ((s * 16) ^ ((r0 & 7) << 4));
    const size_t gs = (size_t)32 * ldk * 2;
#pragma unroll
    for (int i = 0; i < nrows / 32; i++)
        cp16(d0 + i * 32 * 128, g + i * gs);
}

__device__ __forceinline__ void issue_chunk(uint32_t buf,
    const f16* A, const f16* B, int K, int m0, int n0, int k0, int tid)
{
    cpa_tile(buf + A_OFF, A, K, m0, k0, tid, 128);
    cpa_tile(buf + B_OFF, B, K, n0, k0, tid, 256);
    CP_COMMIT();
}

// ---------------------------------------------------------------------------
// GEMM: D[M,N] = A[M,K] @ W[N,K]^T + bias (opt relu), fp16 operands.
//   outputs: fp32 C (if non-null) and/or fp16 Ch (if non-null)
// ---------------------------------------------------------------------------
__global__ __launch_bounds__(256, 1)
void gemm_mma(const f16* __restrict__ A, const f16* __restrict__ B,
              const float* __restrict__ bias,
              float* __restrict__ C, f16* __restrict__ Ch,
              int M, int N, int K, int relu)
{
    extern __shared__ char smem[];
    const uint32_t sb = smem_u32(smem);

    const int tid = threadIdx.x;
    const int l   = tid & 31;
    const int w   = tid >> 5;
    const int mw  = w >> 2;
    const int nw  = w & 3;
    const int m0  = blockIdx.y * 128;
    const int n0  = blockIdx.x * 256;

    const uint32_t swz  = (uint32_t)((l & 7) << 4);
    const uint32_t ak   = (uint32_t)((l >> 4) << 4);
    const uint32_t bk   = (uint32_t)(((l >> 3) & 1) << 4);
    const uint32_t rowA = (uint32_t)((mw * 64 + (l & 15)) * 128);
    const uint32_t rowB = (uint32_t)((nw * 64 + ((l >> 4) << 3) + (l & 7)) * 128);

    float acc[4][8][4];
#pragma unroll
    for (int i = 0; i < 4; i++)
#pragma unroll
        for (int j = 0; j < 8; j++)
#pragma unroll
            for (int q = 0; q < 4; q++) acc[i][j][q] = 0.f;

    const int NC = K >> 6;

    issue_chunk(sb,              A, B, K, m0, n0, 0,  tid);
    if (NC > 1)
        issue_chunk(sb + BUF_STRIDE, A, B, K, m0, n0, 64, tid);

    for (int c = 0; c < NC; c++) {
        const uint32_t bufb = sb + (c % 3) * BUF_STRIDE;

        if (c + 1 < NC) CP_WAIT1(); else CP_WAIT0();
        __syncthreads();

        if (c + 2 < NC)
            issue_chunk(sb + ((c + 2) % 3) * BUF_STRIDE, A, B, K, m0, n0, (c + 2) << 6, tid);

#pragma unroll
        for (int kk = 0; kk < 4; kk++) {
            const uint32_t kbB = ((uint32_t)(kk * 32) | bk) ^ swz;
            const uint32_t kbA = ((uint32_t)(kk * 32) | ak) ^ swz;

            uint32_t bh[16];
            const uint32_t bB = bufb + B_OFF + rowB + kbB;
#pragma unroll
            for (int j = 0; j < 4; j++)
                ldsm4(bh + 4 * j, bB + j * 2048);

            const uint32_t aB = bufb + A_OFF + rowA + kbA;
#pragma unroll
            for (int mt = 0; mt < 4; mt++) {
                uint32_t ah[4];
                ldsm4(ah, aB + mt * 2048);
#pragma unroll
                for (int nt = 0; nt < 8; nt++) mma16816(acc[mt][nt], ah, bh + nt * 2);
            }
        }
    }

    // epilogue
    const int row_base = m0 + mw * 64 + (l >> 2);
    const int col_base = n0 + nw * 64 + 2 * (l & 3);
#pragma unroll
    for (int mt = 0; mt < 4; mt++) {
        const int row = row_base + mt * 16;
#pragma unroll
        for (int nt = 0; nt < 8; nt++) {
            const int col = col_base + nt * 8;
            const float2 bv = *(const float2*)(bias + col);
            float r[4];
            r[0] = acc[mt][nt][0] + bv.x;  r[1] = acc[mt][nt][1] + bv.y;
            r[2] = acc[mt][nt][2] + bv.x;  r[3] = acc[mt][nt][3] + bv.y;
            if (relu) {
#pragma unroll
                for (int q = 0; q < 4; q++) r[q] = fmaxf(r[q], 0.f);
            }
            if (C) {
                *(float2*)(C + (size_t)row * N + col)       = make_float2(r[0], r[1]);
                *(float2*)(C + (size_t)(row + 8) * N + col) = make_float2(r[2], r[3]);
            }
            if (Ch) {
                __half2 h0 = __floats2half2_rn(r[0], r[1]);
                __half2 h1 = __floats2half2_rn(r[2], r[3]);
                *(__half2*)(Ch + (size_t)row * N + col)       = h0;
                *(__half2*)(Ch + (size_t)(row + 8) * N + col) = h1;
            }
        }
    }
}

// ---------------------------------------------------------------------------
// Attention: one block per query row m, warp = head. S=8, dh=64, scale=0.125
// fp16 in (projected Q/K/V), fp32 math, fp16 out.
// ---------------------------------------------------------------------------
__global__ __launch_bounds__(256)
void attn_kernel(const f16* __restrict__ Qp, const f16* __restrict__ Kp,
                 const f16* __restrict__ Vp, f16* __restrict__ out)
{
    const int m = blockIdx.x;
    const int w = threadIdx.x >> 5;
    const int l = threadIdx.x & 31;

    const size_t qoff = (size_t)m * Hdim + w * 64;
    const float q0 = __half2float(Qp[qoff + l]);
    const float q1 = __half2float(Qp[qoff + l + 32]);

    float s[8];
#pragma unroll
    for (int c = 0; c < 8; c++) {
        const f16* k = Kp + ((size_t)m * 8 + c) * Hdim + w * 64;
        float p = q0 * __half2float(k[l]) + q1 * __half2float(k[l + 32]);
#pragma unroll
        for (int o = 16; o > 0; o >>= 1)
            p += __shfl_xor_sync(0xffffffffu, p, o);
        s[c] = p * 0.125f;
    }

    float mx = s[0];
#pragma unroll
    for (int c = 1; c < 8; c++) mx = fmaxf(mx, s[c]);
    float sum = 0.f;
#pragma unroll
    for (int c = 0; c < 8; c++) { s[c] = __expf(s[c] - mx); sum += s[c]; }
    const float inv = 1.f / sum;

    float o0 = 0.f, o1 = 0.f;
#pragma unroll
    for (int c = 0; c < 8; c++) {
        const f16* v = Vp + ((size_t)m * 8 + c) * Hdim + w * 64;
        const float p = s[c] * inv;
        o0 += p * __half2float(v[l]);
        o1 += p * __half2float(v[l + 32]);
    }
    out[qoff + l]      = __float2half_rn(o0);
    out[qoff + l + 32] = __float2half_rn(o1);
}

// ---------------------------------------------------------------------------
// LayerNorm(x + r) over H=512, one block (256 threads) per row.
// Optionally also emits an fp16 copy of the result.
// ---------------------------------------------------------------------------
__global__ __launch_bounds__(256)
void ln_residual_kernel(const float* __restrict__ x, const float* __restrict__ r,
                        const float* __restrict__ g, const float* __restrict__ bt,
                        float* __restrict__ out, f16* __restrict__ oh)
{
    __shared__ float red[16];
    const int m = blockIdx.x;
    const int t = threadIdx.x;
    const int l = t & 31;
    const int w = t >> 5;
    const size_t base = (size_t)m * Hdim;

    const float s0 = x[base + t]       + r[base + t];
    const float s1 = x[base + t + 256] + r[base + t + 256];

    float v = s0 + s1;
#pragma unroll
    for (int o = 16; o > 0; o >>= 1) v += __shfl_xor_sync(0xffffffffu, v, o);
    if (l == 0) red[w] = v;
    __syncthreads();
    float mean = 0.f;
#pragma unroll
    for (int i = 0; i < 8; i++) mean += red[i];
    mean *= (1.f / 512.f);

    const float d0 = s0 - mean, d1 = s1 - mean;
    float vv = d0 * d0 + d1 * d1;
#pragma unroll
    for (int o = 16; o > 0; o >>= 1) vv += __shfl_xor_sync(0xffffffffu, vv, o);
    if (l == 0) red[8 + w] = vv;
    __syncthreads();
    float var = 0.f;
#pragma unroll
    for (int i = 0; i < 8; i++) var += red[8 + i];
    var *= (1.f / 512.f);
    const float rstd = rsqrtf(var + 1e-5f);

    const float y0 = d0 * rstd * g[t]       + bt[t];
    const float y1 = d1 * rstd * g[t + 256] + bt[t + 256];
    out[base + t]       = y0;
    out[base + t + 256] = y1;
    if (oh) {
        oh[base + t]       = __float2half_rn(y0);
        oh[base + t + 256] = __float2half_rn(y1);
    }
}

// ---------------------------------------------------------------------------
extern "C" void kernel_launch(void* const* d_in, const int* in_sizes, int n_in,
                              void* d_out, int out_size)
{
    (void)in_sizes; (void)n_in; (void)out_size;
    const float* query = (const float*)d_in[0];
    const float* key   = (const float*)d_in[1];
    const float* value = (const float*)d_in[2];
    const float* Wq    = (const float*)d_in[3];
    const float* bq    = (const float*)d_in[4];
    const float* Wk    = (const float*)d_in[5];
    const float* bk    = (const float*)d_in[6];
    const float* Wv    = (const float*)d_in[7];
    const float* bv    = (const float*)d_in[8];
    const float* Wo    = (const float*)d_in[9];
    const float* bo    = (const float*)d_in[10];
    const float* ln1g  = (const float*)d_in[11];
    const float* ln1b  = (const float*)d_in[12];
    const float* W1    = (const float*)d_in[13];
    const float* b1    = (const float*)d_in[14];
    const float* W2    = (const float*)d_in[15];
    const float* b2    = (const float*)d_in[16];
    const float* ln2g  = (const float*)d_in[17];
    const float* ln2b  = (const float*)d_in[18];
    float* out = (float*)d_out;

    float *x, *h1;
    cudaGetSymbolAddress((void**)&x,  g_x);
    cudaGetSymbolAddress((void**)&h1, g_h1);

    f16 *q16,*k16,*v16,*Qp,*Kp,*Vp,*at16,*h1h,*f1h;
    f16 *wq,*wk,*wv,*wo,*w1,*w2;
    cudaGetSymbolAddress((void**)&q16, g_q16);
    cudaGetSymbolAddress((void**)&k16, g_k16);
    cudaGetSymbolAddress((void**)&v16, g_v16);
    cudaGetSymbolAddress((void**)&Qp,  g_Qp16);
    cudaGetSymbolAddress((void**)&Kp,  g_Kp16);
    cudaGetSymbolAddress((void**)&Vp,  g_Vp16);
    cudaGetSymbolAddress((void**)&at16,g_at16);
    cudaGetSymbolAddress((void**)&h1h, g_h1h);
    cudaGetSymbolAddress((void**)&f1h, g_f1h);
    cudaGetSymbolAddress((void**)&wq,  g_wq16);
    cudaGetSymbolAddress((void**)&wk,  g_wk16);
    cudaGetSymbolAddress((void**)&wv,  g_wv16);
    cudaGetSymbolAddress((void**)&wo,  g_wo16);
    cudaGetSymbolAddress((void**)&w1,  g_w116);
    cudaGetSymbolAddress((void**)&w2,  g_w216);

    cudaFuncSetAttribute(gemm_mma, cudaFuncAttributeMaxDynamicSharedMemorySize, SMEM_GEMM);

    #define CVT1(src, hi, n) \
        cvt_h16<<<((n)/4 + 255)/256, 256>>>((const float4*)(src), (uint2*)(hi), (n)/4)

    // weights -> fp16
    CVT1(Wq, wq, Hdim*Hdim);
    CVT1(Wk, wk, Hdim*Hdim);
    CVT1(Wv, wv, Hdim*Hdim);
    CVT1(Wo, wo, Hdim*Hdim);
    CVT1(W1, w1, HF*Hdim);
    CVT1(W2, w2, Hdim*HF);

    // activations -> fp16
    CVT1(query, q16, M_Q*Hdim);
    CVT1(key,   k16, M_KV*Hdim);
    CVT1(value, v16, M_KV*Hdim);

    // Q/K/V projections (fp16 out)
    gemm_mma<<<dim3(Hdim/256, M_Q /128), 256, SMEM_GEMM>>>(q16, wq, bq, 0, Qp, M_Q,  Hdim, Hdim, 0);
    gemm_mma<<<dim3(Hdim/256, M_KV/128), 256, SMEM_GEMM>>>(k16, wk, bk, 0, Kp, M_KV, Hdim, Hdim, 0);
    gemm_mma<<<dim3(Hdim/256, M_KV/128), 256, SMEM_GEMM>>>(v16, wv, bv, 0, Vp, M_KV, Hdim, Hdim, 0);

    // attention (fp16 in/out)
    attn_kernel<<<M_Q, 256>>>(Qp, Kp, Vp, at16);

    // O projection (fp32 out) + residual + LN1 (fp32 + fp16 copy)
    gemm_mma<<<dim3(Hdim/256, M_Q/128), 256, SMEM_GEMM>>>(at16, wo, bo, x, 0, M_Q, Hdim, Hdim, 0);
    ln_residual_kernel<<<M_Q, 256>>>(x, query, ln1g, ln1b, h1, h1h);

    // FFN1 (relu, fp16 out) -> FFN2 (fp32 out) -> LN2 (final out)
    gemm_mma<<<dim3(HF/256, M_Q/128), 256, SMEM_GEMM>>>(h1h, w1, b1, 0, f1h, M_Q, HF, Hdim, 1);
    gemm_mma<<<dim3(Hdim/256, M_Q/128), 256, SMEM_GEMM>>>(f1h, w2, b2, x, 0, M_Q, Hdim, HF, 0);
    ln_residual_kernel<<<M_Q, 256>>>(x, h1, ln2g, ln2b, out, 0);
}

// round 8
// speedup vs baseline: 3.6203x; 1.5572x over previous
#include <cuda_runtime.h>
#include <cuda_fp16.h>
#include <cstdint>

// ---------------------------------------------------------------------------
// AttentionEncoderLayer: B=4, C=8, F=2048, H=512, NH=8, dh=64, Hf=1024
//   M = F*B = 8192 query rows; key/value flat [65536,512];
//   query row m attends KV rows [8m, 8m+8).
// Folded attention algebra (softmax shift-invariance + linearity):
//   scores: s_h[m,c] = (Qp_h[m] @ Wk_h) . k[8m+c]        (bk drops out)
//   values: x_h[m]   = (sum_c att_c v[8m+c]) @ Wv_h^T    (bv -> output bias)
// so the two 65536-row projections (72% of FLOPs) never happen.
// GEMMs: 1-pass fp16 HMMA (fp32 accum), measured floor ~12cyc/HMMA/SMSP.
// ---------------------------------------------------------------------------

#define M_Q   8192
#define Hdim  512
#define HF    1024

typedef __half f16;

// fp32 spine
__device__ float g_x  [M_Q * Hdim];
__device__ float g_h1 [M_Q * Hdim];

// fp16 buffers
__device__ f16 g_q16 [M_Q * Hdim];
__device__ f16 g_Qp16[M_Q * Hdim];
__device__ f16 g_Qt  [M_Q * 8 * Hdim];     // [m, h*512+d]
__device__ f16 g_Y2  [8 * M_Q * Hdim];     // [h*8192+m, d]  (per-head mixed v)
__device__ f16 g_x16 [M_Q * Hdim];
__device__ f16 g_h1h [M_Q * Hdim];
__device__ f16 g_f1h [M_Q * HF  ];
__device__ f16 g_wq16[Hdim * Hdim];
__device__ f16 g_wkT [Hdim * Hdim];        // Wk transposed
__device__ f16 g_wv16[Hdim * Hdim];
__device__ f16 g_wo16[Hdim * Hdim];
__device__ f16 g_w116[HF * Hdim];
__device__ f16 g_w216[Hdim * HF];

// ---------------- helpers ----------------
__device__ __forceinline__ uint32_t smem_u32(const void* p) {
    uint32_t a;
    asm("{ .reg .u64 t; cvta.to.shared.u64 t, %1; cvt.u32.u64 %0, t; }" : "=r"(a) : "l"(p));
    return a;
}
__device__ __forceinline__ void ldsm4(uint32_t* r, uint32_t addr) {
    asm volatile("ldmatrix.sync.aligned.m8n8.x4.shared.b16 {%0,%1,%2,%3}, [%4];"
                 : "=r"(r[0]), "=r"(r[1]), "=r"(r[2]), "=r"(r[3]) : "r"(addr));
}
__device__ __forceinline__ void mma16816(float* d, const uint32_t* a, const uint32_t* b) {
    asm volatile("mma.sync.aligned.m16n8k16.row.col.f32.f16.f16.f32 "
                 "{%0,%1,%2,%3}, {%4,%5,%6,%7}, {%8,%9}, {%0,%1,%2,%3};"
                 : "+f"(d[0]), "+f"(d[1]), "+f"(d[2]), "+f"(d[3])
                 : "r"(a[0]), "r"(a[1]), "r"(a[2]), "r"(a[3]), "r"(b[0]), "r"(b[1]));
}
__device__ __forceinline__ void cp16(uint32_t dst, const void* src) {
    asm volatile("cp.async.cg.shared.global [%0], [%1], 16;" :: "r"(dst), "l"(src));
}
#define CP_COMMIT() asm volatile("cp.async.commit_group;" ::: "memory")
#define CP_WAIT1()  asm volatile("cp.async.wait_group 1;" ::: "memory")
#define CP_WAIT0()  asm volatile("cp.async.wait_group 0;" ::: "memory")

// ---------------------------------------------------------------------------
// prepass: fp32 -> fp16 (optionally transposed)
// ---------------------------------------------------------------------------
__global__ __launch_bounds__(256)
void cvt_h16(const float4* __restrict__ src, uint2* __restrict__ hi, int n4)
{
    const int i = blockIdx.x * 256 + threadIdx.x;
    if (i >= n4) return;
    const float4 x = src[i];
    __half2 h01 = __floats2half2_rn(x.x, x.y);
    __half2 h23 = __floats2half2_rn(x.z, x.w);
    hi[i] = make_uint2(*(uint32_t*)&h01, *(uint32_t*)&h23);
}

// dst[c, r] = src[r, c];  src is RxC.  grid (R/32, C/32), 256 threads.
__global__ __launch_bounds__(256)
void cvt_t16(const float* __restrict__ src, f16* __restrict__ dst, int R, int C)
{
    __shared__ float t[32][33];
    const int bi = blockIdx.x * 32, bj = blockIdx.y * 32;
    const int tx = threadIdx.x & 31, ty = threadIdx.x >> 5;
#pragma unroll
    for (int i = 0; i < 32; i += 8)
        t[ty + i][tx] = src[(size_t)(bi + ty + i) * C + bj + tx];
    __syncthreads();
#pragma unroll
    for (int i = 0; i < 32; i += 8)
        dst[(size_t)(bj + ty + i) * R + bi + tx] = __float2half_rn(t[tx][ty + i]);
}

// ---------------------------------------------------------------------------
// std GEMM: C[m,n] = sum_k A[m,k]*B[n,k] + bias[n]   (fp16 in, fp32 accum)
// BM=128 BN=256 BK=64, 8 warps (2m x 4n, 64x64 each), 3-stage cp.async.
// Per-z (grid.z) element offsets for grouped/per-head launches.
// ---------------------------------------------------------------------------
#define A_OFF 0
#define B_OFF 16384
#define BUF_STRIDE 49152
#define SMEM_GEMM (3 * BUF_STRIDE)

__device__ __forceinline__ void cpa_tile(uint32_t dst, const f16* __restrict__ src,
                                         int ldk, int row0, int k0, int tid, int nrows)
{
    const int s  = tid & 7;
    const int r0 = tid >> 3;
    const char* g = (const char*)(src + (size_t)(row0 + r0) * ldk + k0) + s * 16;
    const uint32_t d0 = dst + r0 * 128 + ((s * 16) ^ ((r0 & 7) << 4));
    const size_t gs = (size_t)32 * ldk * 2;
#pragma unroll
    for (int i = 0; i < nrows / 32; i++)
        cp16(d0 + i * 32 * 128, g + i * gs);
}

__global__ __launch_bounds__(256, 1)
void gemm_std(const f16* __restrict__ A, int lda, long zA,
              const f16* __restrict__ B, int ldb, long zB,
              const float* __restrict__ bias, int zBias,
              float* __restrict__ C, f16* __restrict__ Ch, int ldc, int zC,
              int K, int relu)
{
    extern __shared__ char smem[];
    const uint32_t sb = smem_u32(smem);

    const int tid = threadIdx.x;
    const int l   = tid & 31;
    const int w   = tid >> 5;
    const int mw  = w >> 2;
    const int nw  = w & 3;
    const int m0  = blockIdx.y * 128;
    const int n0  = blockIdx.x * 256;
    const int z   = blockIdx.z;

    A += (long)z * zA;
    B += (long)z * zB;
    if (bias) bias += (long)z * zBias;
    const size_t cz = (size_t)z * zC;

    const uint32_t swz  = (uint32_t)((l & 7) << 4);
    const uint32_t ak   = (uint32_t)((l >> 4) << 4);
    const uint32_t bk   = (uint32_t)(((l >> 3) & 1) << 4);
    const uint32_t rowA = (uint32_t)((mw * 64 + (l & 15)) * 128);
    const uint32_t rowB = (uint32_t)((nw * 64 + ((l >> 4) << 3) + (l & 7)) * 128);

    float acc[4][8][4];
#pragma unroll
    for (int i = 0; i < 4; i++)
#pragma unroll
        for (int j = 0; j < 8; j++)
#pragma unroll
            for (int q = 0; q < 4; q++) acc[i][j][q] = 0.f;

    const int NC = K >> 6;

    cpa_tile(sb + A_OFF, A, lda, m0, 0, tid, 128);
    cpa_tile(sb + B_OFF, B, ldb, n0, 0, tid, 256);
    CP_COMMIT();
    if (NC > 1) {
        cpa_tile(sb + BUF_STRIDE + A_OFF, A, lda, m0, 64, tid, 128);
        cpa_tile(sb + BUF_STRIDE + B_OFF, B, ldb, n0, 64, tid, 256);
        CP_COMMIT();
    }

    for (int c = 0; c < NC; c++) {
        const uint32_t bufb = sb + (c % 3) * BUF_STRIDE;

        if (c + 1 < NC) CP_WAIT1(); else CP_WAIT0();
        __syncthreads();

        if (c + 2 < NC) {
            const uint32_t bn = sb + ((c + 2) % 3) * BUF_STRIDE;
            cpa_tile(bn + A_OFF, A, lda, m0, (c + 2) << 6, tid, 128);
            cpa_tile(bn + B_OFF, B, ldb, n0, (c + 2) << 6, tid, 256);
            CP_COMMIT();
        }

#pragma unroll
        for (int kk = 0; kk < 4; kk++) {
            const uint32_t kbB = ((uint32_t)(kk * 32) | bk) ^ swz;
            const uint32_t kbA = ((uint32_t)(kk * 32) | ak) ^ swz;

            uint32_t bh[16];
            const uint32_t bB = bufb + B_OFF + rowB + kbB;
#pragma unroll
            for (int j = 0; j < 4; j++)
                ldsm4(bh + 4 * j, bB + j * 2048);

            const uint32_t aB = bufb + A_OFF + rowA + kbA;
#pragma unroll
            for (int mt = 0; mt < 4; mt++) {
                uint32_t ah[4];
                ldsm4(ah, aB + mt * 2048);
#pragma unroll
                for (int nt = 0; nt < 8; nt++) mma16816(acc[mt][nt], ah, bh + nt * 2);
            }
        }
    }

    const int row_base = m0 + mw * 64 + (l >> 2);
    const int col_base = n0 + nw * 64 + 2 * (l & 3);
#pragma unroll
    for (int mt = 0; mt < 4; mt++) {
        const int row = row_base + mt * 16;
#pragma unroll
        for (int nt = 0; nt < 8; nt++) {
            const int col = col_base + nt * 8;
            float2 bv = bias ? *(const float2*)(bias + col) : make_float2(0.f, 0.f);
            float r[4];
            r[0] = acc[mt][nt][0] + bv.x;  r[1] = acc[mt][nt][1] + bv.y;
            r[2] = acc[mt][nt][2] + bv.x;  r[3] = acc[mt][nt][3] + bv.y;
            if (relu) {
#pragma unroll
                for (int q = 0; q < 4; q++) r[q] = fmaxf(r[q], 0.f);
            }
            if (C) {
                *(float2*)(C + cz + (size_t)row * ldc + col)       = make_float2(r[0], r[1]);
                *(float2*)(C + cz + (size_t)(row + 8) * ldc + col) = make_float2(r[2], r[3]);
            }
            if (Ch) {
                __half2 h0 = __floats2half2_rn(r[0], r[1]);
                __half2 h1 = __floats2half2_rn(r[2], r[3]);
                *(__half2*)(Ch + cz + (size_t)row * ldc + col)       = h0;
                *(__half2*)(Ch + cz + (size_t)(row + 8) * ldc + col) = h1;
            }
        }
    }
}

// ---------------------------------------------------------------------------
// narrow GEMM: BM=128, BN=64, 8 warps (4m x 2n, 32x32 each), for per-head
// V-mix projection (grid.z = head).
// ---------------------------------------------------------------------------
#define NA_OFF 0
#define NB_OFF 16384
#define NBUF_STRIDE 24576
#define SMEM_GEMM_N (3 * NBUF_STRIDE)

__global__ __launch_bounds__(256, 2)
void gemm_n64(const f16* __restrict__ A, int lda, long zA,
              const f16* __restrict__ B, int ldb, long zB,
              const float* __restrict__ bias, int zBias,
              f16* __restrict__ Ch, int ldc, int zC,
              int K)
{
    extern __shared__ char smem[];
    const uint32_t sb = smem_u32(smem);

    const int tid = threadIdx.x;
    const int l   = tid & 31;
    const int w   = tid >> 5;
    const int mw  = w >> 1;     // 0..3
    const int nw  = w & 1;      // 0..1
    const int m0  = blockIdx.y * 128;
    const int z   = blockIdx.z;

    A += (long)z * zA;
    B += (long)z * zB;
    bias += (long)z * zBias;
    const size_t cz = (size_t)z * zC;

    const uint32_t swz  = (uint32_t)((l & 7) << 4);
    const uint32_t ak   = (uint32_t)((l >> 4) << 4);
    const uint32_t bk   = (uint32_t)(((l >> 3) & 1) << 4);
    const uint32_t rowA = (uint32_t)((mw * 32 + (l & 15)) * 128);
    uint32_t rowB[2];
#pragma unroll
    for (int nt2 = 0; nt2 < 2; nt2++)
        rowB[nt2] = (uint32_t)((nw * 32 + nt2 * 16 + ((l >> 4) << 3) + (l & 7)) * 128);

    float acc[2][4][4];
#pragma unroll
    for (int i = 0; i < 2; i++)
#pragma unroll
        for (int j = 0; j < 4; j++)
#pragma unroll
            for (int q = 0; q < 4; q++) acc[i][j][q] = 0.f;

    const int NC = K >> 6;

    cpa_tile(sb + NA_OFF, A, lda, m0, 0, tid, 128);
    cpa_tile(sb + NB_OFF, B, ldb, 0,  0, tid, 64);
    CP_COMMIT();
    if (NC > 1) {
        cpa_tile(sb + NBUF_STRIDE + NA_OFF, A, lda, m0, 64, tid, 128);
        cpa_tile(sb + NBUF_STRIDE + NB_OFF, B, ldb, 0,  64, tid, 64);
        CP_COMMIT();
    }

    for (int c = 0; c < NC; c++) {
        const uint32_t bufb = sb + (c % 3) * NBUF_STRIDE;

        if (c + 1 < NC) CP_WAIT1(); else CP_WAIT0();
        __syncthreads();

        if (c + 2 < NC) {
            const uint32_t bn = sb + ((c + 2) % 3) * NBUF_STRIDE;
            cpa_tile(bn + NA_OFF, A, lda, m0, (c + 2) << 6, tid, 128);
            cpa_tile(bn + NB_OFF, B, ldb, 0,  (c + 2) << 6, tid, 64);
            CP_COMMIT();
        }

#pragma unroll
        for (int kk = 0; kk < 4; kk++) {
            const uint32_t kbB = ((uint32_t)(kk * 32) | bk) ^ swz;
            const uint32_t kbA = ((uint32_t)(kk * 32) | ak) ^ swz;

            uint32_t bh[8];
            ldsm4(bh + 0, bufb + NB_OFF + rowB[0] + kbB);
            ldsm4(bh + 4, bufb + NB_OFF + rowB[1] + kbB);

            const uint32_t aB = bufb + NA_OFF + rowA + kbA;
#pragma unroll
            for (int mt = 0; mt < 2; mt++) {
                uint32_t ah[4];
                ldsm4(ah, aB + mt * 2048);
#pragma unroll
                for (int nt = 0; nt < 4; nt++) mma16816(acc[mt][nt], ah, bh + nt * 2);
            }
        }
    }

    const int row_base = m0 + mw * 32 + (l >> 2);
    const int col_base = nw * 32 + 2 * (l & 3);
#pragma unroll
    for (int mt = 0; mt < 2; mt++) {
        const int row = row_base + mt * 16;
#pragma unroll
        for (int nt = 0; nt < 4; nt++) {
            const int col = col_base + nt * 8;
            const float2 bv = *(const float2*)(bias + col);
            __half2 h0 = __floats2half2_rn(acc[mt][nt][0] + bv.x, acc[mt][nt][1] + bv.y);
            __half2 h1 = __floats2half2_rn(acc[mt][nt][2] + bv.x, acc[mt][nt][3] + bv.y);
            *(__half2*)(Ch + cz + (size_t)row * ldc + col)       = h0;
            *(__half2*)(Ch + cz + (size_t)(row + 8) * ldc + col) = h1;
        }
    }
}

// ---------------------------------------------------------------------------
// Attention core: block = query row m, warp = head h.
//   s_h[c] = Qt_h[m] . k[8m+c] / 8   (512-dim dot, raw fp32 k)
//   y_h    = sum_c softmax(s)_c * v[8m+c]   -> Y2[h*8192+m, :]  (fp16)
// ---------------------------------------------------------------------------
__global__ __launch_bounds__(256)
void attn_kernel(const f16* __restrict__ Qt, const float* __restrict__ key,
                 const float* __restrict__ value, f16* __restrict__ Y2)
{
    __shared__ float ks[8][512];
    __shared__ float vs[8][512];
    const int m = blockIdx.x;
    const int t = threadIdx.x;

    const float4* kg = (const float4*)(key   + (size_t)m * 8 * 512);
    const float4* vg = (const float4*)(value + (size_t)m * 8 * 512);
    float4* ksm = (float4*)ks;
    float4* vsm = (float4*)vs;
#pragma unroll
    for (int i = 0; i < 4; i++) {
        ksm[t + 256 * i] = kg[t + 256 * i];
        vsm[t + 256 * i] = vg[t + 256 * i];
    }
    __syncthreads();

    const int h = t >> 5, l = t & 31;

    const __half2* qtp = (const __half2*)(Qt + (size_t)m * 4096 + h * 512);
    float2 q2[8];
#pragma unroll
    for (int j = 0; j < 8; j++) q2[j] = __half22float2(qtp[l + 32 * j]);

    float s[8];
#pragma unroll
    for (int c = 0; c < 8; c++) {
        float p = 0.f;
#pragma unroll
        for (int j = 0; j < 8; j++) {
            const float2 kk = *(const float2*)&ks[c][64 * j + 2 * l];
            p += q2[j].x * kk.x + q2[j].y * kk.y;
        }
#pragma unroll
        for (int o = 16; o > 0; o >>= 1) p += __shfl_xor_sync(0xffffffffu, p, o);
        s[c] = p * 0.125f;
    }

    float mx = s[0];
#pragma unroll
    for (int c = 1; c < 8; c++) mx = fmaxf(mx, s[c]);
    float sum = 0.f;
#pragma unroll
    for (int c = 0; c < 8; c++) { s[c] = __expf(s[c] - mx); sum += s[c]; }
    const float inv = 1.f / sum;
#pragma unroll
    for (int c = 0; c < 8; c++) s[c] *= inv;

    __half2* yp = (__half2*)(Y2 + ((size_t)h * M_Q + m) * 512);
#pragma unroll
    for (int j = 0; j < 8; j++) {
        float2 a = make_float2(0.f, 0.f);
#pragma unroll
        for (int c = 0; c < 8; c++) {
            const float2 vv = *(const float2*)&vs[c][64 * j + 2 * l];
            a.x += s[c] * vv.x;
            a.y += s[c] * vv.y;
        }
        yp[l + 32 * j] = __floats2half2_rn(a.x, a.y);
    }
}

// ---------------------------------------------------------------------------
// LayerNorm(x + r), H=512, one block per row; optional fp16 copy.
// ---------------------------------------------------------------------------
__global__ __launch_bounds__(256)
void ln_residual_kernel(const float* __restrict__ x, const float* __restrict__ r,
                        const float* __restrict__ g, const float* __restrict__ bt,
                        float* __restrict__ out, f16* __restrict__ oh)
{
    __shared__ float red[16];
    const int m = blockIdx.x;
    const int t = threadIdx.x;
    const int l = t & 31;
    const int w = t >> 5;
    const size_t base = (size_t)m * Hdim;

    const float s0 = x[base + t]       + r[base + t];
    const float s1 = x[base + t + 256] + r[base + t + 256];

    float v = s0 + s1;
#pragma unroll
    for (int o = 16; o > 0; o >>= 1) v += __shfl_xor_sync(0xffffffffu, v, o);
    if (l == 0) red[w] = v;
    __syncthreads();
    float mean = 0.f;
#pragma unroll
    for (int i = 0; i < 8; i++) mean += red[i];
    mean *= (1.f / 512.f);

    const float d0 = s0 - mean, d1 = s1 - mean;
    float vv = d0 * d0 + d1 * d1;
#pragma unroll
    for (int o = 16; o > 0; o >>= 1) vv += __shfl_xor_sync(0xffffffffu, vv, o);
    if (l == 0) red[8 + w] = vv;
    __syncthreads();
    float var = 0.f;
#pragma unroll
    for (int i = 0; i < 8; i++) var += red[8 + i];
    var *= (1.f / 512.f);
    const float rstd = rsqrtf(var + 1e-5f);

    const float y0 = d0 * rstd * g[t]       + bt[t];
    const float y1 = d1 * rstd * g[t + 256] + bt[t + 256];
    out[base + t]       = y0;
    out[base + t + 256] = y1;
    if (oh) {
        oh[base + t]       = __float2half_rn(y0);
        oh[base + t + 256] = __float2half_rn(y1);
    }
}

// ---------------------------------------------------------------------------
extern "C" void kernel_launch(void* const* d_in, const int* in_sizes, int n_in,
                              void* d_out, int out_size)
{
    (void)in_sizes; (void)n_in; (void)out_size;
    const float* query = (const float*)d_in[0];
    const float* key   = (const float*)d_in[1];
    const float* value = (const float*)d_in[2];
    const float* Wq    = (const float*)d_in[3];
    const float* bq    = (const float*)d_in[4];
    const float* Wk    = (const float*)d_in[5];
    const float* bv    = (const float*)d_in[8];
    const float* Wv    = (const float*)d_in[7];
    const float* Wo    = (const float*)d_in[9];
    const float* bo    = (const float*)d_in[10];
    const float* ln1g  = (const float*)d_in[11];
    const float* ln1b  = (const float*)d_in[12];
    const float* W1    = (const float*)d_in[13];
    const float* b1    = (const float*)d_in[14];
    const float* W2    = (const float*)d_in[15];
    const float* b2    = (const float*)d_in[16];
    const float* ln2g  = (const float*)d_in[17];
    const float* ln2b  = (const float*)d_in[18];
    float* out = (float*)d_out;

    float *x, *h1;
    cudaGetSymbolAddress((void**)&x,  g_x);
    cudaGetSymbolAddress((void**)&h1, g_h1);

    f16 *q16,*Qp,*Qt,*Y2,*x16,*h1h,*f1h;
    f16 *wq,*wkT,*wv,*wo,*w1,*w2;
    cudaGetSymbolAddress((void**)&q16, g_q16);
    cudaGetSymbolAddress((void**)&Qp,  g_Qp16);
    cudaGetSymbolAddress((void**)&Qt,  g_Qt);
    cudaGetSymbolAddress((void**)&Y2,  g_Y2);
    cudaGetSymbolAddress((void**)&x16, g_x16);
    cudaGetSymbolAddress((void**)&h1h, g_h1h);
    cudaGetSymbolAddress((void**)&f1h, g_f1h);
    cudaGetSymbolAddress((void**)&wq,  g_wq16);
    cudaGetSymbolAddress((void**)&wkT, g_wkT);
    cudaGetSymbolAddress((void**)&wv,  g_wv16);
    cudaGetSymbolAddress((void**)&wo,  g_wo16);
    cudaGetSymbolAddress((void**)&w1,  g_w116);
    cudaGetSymbolAddress((void**)&w2,  g_w216);

    cudaFuncSetAttribute(gemm_std, cudaFuncAttributeMaxDynamicSharedMemorySize, SMEM_GEMM);
    cudaFuncSetAttribute(gemm_n64, cudaFuncAttributeMaxDynamicSharedMemorySize, SMEM_GEMM_N);

    #define CVT1(src, hi, n) \
        cvt_h16<<<((n)/4 + 255)/256, 256>>>((const float4*)(src), (uint2*)(hi), (n)/4)

    // weights
    CVT1(Wq, wq, Hdim*Hdim);
    CVT1(Wv, wv, Hdim*Hdim);
    CVT1(Wo, wo, Hdim*Hdim);
    CVT1(W1, w1, HF*Hdim);
    CVT1(W2, w2, Hdim*HF);
    cvt_t16<<<dim3(16, 16), 256>>>(Wk, wkT, Hdim, Hdim);
    CVT1(query, q16, M_Q*Hdim);

    // Qp = q16 @ Wq^T + bq   (fp16)
    gemm_std<<<dim3(2, 64, 1), 256, SMEM_GEMM>>>(
        q16, Hdim, 0, wq, Hdim, 0, bq, 0, 0, Qp, Hdim, 0, Hdim, 0);

    // Qt_h = Qp_h @ Wk rows(h)   (grid.z = head, K=64, no bias)
    gemm_std<<<dim3(2, 64, 8), 256, SMEM_GEMM>>>(
        Qp, Hdim, 64, wkT, Hdim, 64, 0, 0, 0, Qt, 8*Hdim, 512, 64, 0);

    // attention: scores vs raw fp32 k, mix raw fp32 v -> Y2
    attn_kernel<<<M_Q, 256>>>(Qt, key, value, Y2);

    // x16[:, h*64:(h+1)*64] = Y2_h @ Wv rows(h)^T + bv_h
    gemm_n64<<<dim3(1, 64, 8), 256, SMEM_GEMM_N>>>(
        Y2, Hdim, (long)M_Q*Hdim, wv, Hdim, (long)64*Hdim, bv, 64,
        x16, Hdim, 64, Hdim);

    // O projection (fp32) + residual + LN1
    gemm_std<<<dim3(2, 64, 1), 256, SMEM_GEMM>>>(
        x16, Hdim, 0, wo, Hdim, 0, bo, 0, x, 0, Hdim, 0, Hdim, 0);
    ln_residual_kernel<<<M_Q, 256>>>(x, query, ln1g, ln1b, h1, h1h);

    // FFN1 (relu, fp16) -> FFN2 (fp32) -> LN2
    gemm_std<<<dim3(4, 64, 1), 256, SMEM_GEMM>>>(
        h1h, Hdim, 0, w1, Hdim, 0, b1, 0, 0, f1h, HF, 0, Hdim, 1);
    gemm_std<<<dim3(2, 64, 1), 256, SMEM_GEMM>>>(
        f1h, HF, 0, w2, HF, 0, b2, 0, x, 0, Hdim, 0, HF, 0);
    ln_residual_kernel<<<M_Q, 256>>>(x, h1, ln2g, ln2b, out, 0);
}

// round 9
// speedup vs baseline: 3.7428x; 1.0338x over previous
#include <cuda_runtime.h>
#include <cuda_fp16.h>
#include <cstdint>

// ---------------------------------------------------------------------------
// AttentionEncoderLayer: B=4, C=8, F=2048, H=512, NH=8, dh=64, Hf=1024
// Folded attention algebra (softmax shift-invariance + linearity):
//   scores: s_h[m,c] = (Qp_h[m] @ Wk_h) . k[8m+c]        (bk drops out)
//   values: x_h[m]   = (sum_c att_c v[8m+c]) @ Wv_h^T    (bv -> output bias)
// GEMMs: 1-pass fp16 HMMA (fp32 accum), rt ~12cyc/HMMA/SMSP floor.
// This round: occupancy-2 GEMM (tile 128x128, warp 64x32, 3-stage, 96KB),
// batched cvt, residual fused into GEMM epilogues.
// ---------------------------------------------------------------------------

#define M_Q   8192
#define Hdim  512
#define HF    1024

typedef __half f16;

// fp32 spine
__device__ float g_x  [M_Q * Hdim];
__device__ float g_h1 [M_Q * Hdim];

// fp16 buffers
__device__ f16 g_q16 [M_Q * Hdim];
__device__ f16 g_Qp16[M_Q * Hdim];
__device__ f16 g_Qt  [M_Q * 8 * Hdim];     // [m, h*512+d]
__device__ f16 g_Y2  [8 * M_Q * Hdim];     // [h*8192+m, d]
__device__ f16 g_x16 [M_Q * Hdim];
__device__ f16 g_h1h [M_Q * Hdim];
__device__ f16 g_f1h [M_Q * HF  ];
__device__ f16 g_wq16[Hdim * Hdim];
__device__ f16 g_wkT [Hdim * Hdim];        // Wk transposed
__device__ f16 g_wv16[Hdim * Hdim];
__device__ f16 g_wo16[Hdim * Hdim];
__device__ f16 g_w116[HF * Hdim];
__device__ f16 g_w216[Hdim * HF];

// ---------------- helpers ----------------
__device__ __forceinline__ uint32_t smem_u32(const void* p) {
    uint32_t a;
    asm("{ .reg .u64 t; cvta.to.shared.u64 t, %1; cvt.u32.u64 %0, t; }" : "=r"(a) : "l"(p));
    return a;
}
__device__ __forceinline__ void ldsm4(uint32_t* r, uint32_t addr) {
    asm volatile("ldmatrix.sync.aligned.m8n8.x4.shared.b16 {%0,%1,%2,%3}, [%4];"
                 : "=r"(r[0]), "=r"(r[1]), "=r"(r[2]), "=r"(r[3]) : "r"(addr));
}
__device__ __forceinline__ void mma16816(float* d, const uint32_t* a, const uint32_t* b) {
    asm volatile("mma.sync.aligned.m16n8k16.row.col.f32.f16.f16.f32 "
                 "{%0,%1,%2,%3}, {%4,%5,%6,%7}, {%8,%9}, {%0,%1,%2,%3};"
                 : "+f"(d[0]), "+f"(d[1]), "+f"(d[2]), "+f"(d[3])
                 : "r"(a[0]), "r"(a[1]), "r"(a[2]), "r"(a[3]), "r"(b[0]), "r"(b[1]));
}
__device__ __forceinline__ void cp16(uint32_t dst, const void* src) {
    asm volatile("cp.async.cg.shared.global [%0], [%1], 16;" :: "r"(dst), "l"(src));
}
#define CP_COMMIT() asm volatile("cp.async.commit_group;" ::: "memory")
#define CP_WAIT1()  asm volatile("cp.async.wait_group 1;" ::: "memory")
#define CP_WAIT0()  asm volatile("cp.async.wait_group 0;" ::: "memory")

// ---------------------------------------------------------------------------
// prepass: fp32 -> fp16; batched over up to 6 segments, plus transpose.
// ---------------------------------------------------------------------------
struct CvtTbl {
    const float4* src[6];
    uint2*        dst[6];
    int           cum[6];   // cumulative n4
    int           njobs;
};

__global__ __launch_bounds__(256)
void cvt_batch(CvtTbl tbl)
{
    int i = blockIdx.x * 256 + threadIdx.x;
    if (i >= tbl.cum[tbl.njobs - 1]) return;
    int j = 0;
#pragma unroll
    for (int q = 0; q < 5; q++) if (j < tbl.njobs - 1 && i >= tbl.cum[j]) j++;
    const int base = (j == 0) ? 0 : tbl.cum[j - 1];
    const int idx = i - base;
    const float4 x = tbl.src[j][idx];
    __half2 h01 = __floats2half2_rn(x.x, x.y);
    __half2 h23 = __floats2half2_rn(x.z, x.w);
    tbl.dst[j][idx] = make_uint2(*(uint32_t*)&h01, *(uint32_t*)&h23);
}

__global__ __launch_bounds__(256)
void cvt_h16(const float4* __restrict__ src, uint2* __restrict__ hi, int n4)
{
    const int i = blockIdx.x * 256 + threadIdx.x;
    if (i >= n4) return;
    const float4 x = src[i];
    __half2 h01 = __floats2half2_rn(x.x, x.y);
    __half2 h23 = __floats2half2_rn(x.z, x.w);
    hi[i] = make_uint2(*(uint32_t*)&h01, *(uint32_t*)&h23);
}

// dst[c, r] = src[r, c]
__global__ __launch_bounds__(256)
void cvt_t16(const float* __restrict__ src, f16* __restrict__ dst, int R, int C)
{
    __shared__ float t[32][33];
    const int bi = blockIdx.x * 32, bj = blockIdx.y * 32;
    const int tx = threadIdx.x & 31, ty = threadIdx.x >> 5;
#pragma unroll
    for (int i = 0; i < 32; i += 8)
        t[ty + i][tx] = src[(size_t)(bi + ty + i) * C + bj + tx];
    __syncthreads();
#pragma unroll
    for (int i = 0; i < 32; i += 8)
        dst[(size_t)(bj + ty + i) * R + bi + tx] = __float2half_rn(t[tx][ty + i]);
}

// ---------------------------------------------------------------------------
// std GEMM: C[m,n] = sum_k A[m,k]*B[n,k] + bias[n] (+res[m,n])
// BM=128 BN=128 BK=64, 8 warps (2m x 4n, warp tile 64x32), 3-stage cp.async,
// occupancy 2 (96KB smem, <=128 regs). Per-z offsets for grouped launches.
// ---------------------------------------------------------------------------
#define A_OFF 0
#define B_OFF 16384
#define BUF_STRIDE 32768
#define SMEM_GEMM (3 * BUF_STRIDE)   // 98304

__device__ __forceinline__ void cpa_tile(uint32_t dst, const f16* __restrict__ src,
                                         int ldk, int row0, int k0, int tid, int nrows)
{
    const int s  = tid & 7;
    const int r0 = tid >> 3;
    const char* g = (const char*)(src + (size_t)(row0 + r0) * ldk + k0) + s * 16;
    const uint32_t d0 = dst + r0 * 128 + ((s * 16) ^ ((r0 & 7) << 4));
    const size_t gs = (size_t)32 * ldk * 2;
#pragma unroll
    for (int i = 0; i < nrows / 32; i++)
        cp16(d0 + i * 32 * 128, g + i * gs);
}

__global__ __launch_bounds__(256, 2)
void gemm_std(const f16* __restrict__ A, int lda, long zA,
              const f16* __restrict__ B, int ldb, long zB,
              const float* __restrict__ bias, int zBias,
              const float* __restrict__ res,
              float* __restrict__ C, f16* __restrict__ Ch, int ldc, int zC,
              int K, int relu)
{
    extern __shared__ char smem[];
    const uint32_t sb = smem_u32(smem);

    const int tid = threadIdx.x;
    const int l   = tid & 31;
    const int w   = tid >> 5;
    const int mw  = w >> 2;      // 0..1 : 64-row half
    const int nw  = w & 3;       // 0..3 : 32-col quarter
    const int m0  = blockIdx.y * 128;
    const int n0  = blockIdx.x * 128;
    const int z   = blockIdx.z;

    A += (long)z * zA;
    B += (long)z * zB;
    if (bias) bias += (long)z * zBias;
    const size_t cz = (size_t)z * zC;

    const uint32_t swz   = (uint32_t)((l & 7) << 4);
    const uint32_t ak    = (uint32_t)((l >> 4) << 4);
    const uint32_t bk    = (uint32_t)(((l >> 3) & 1) << 4);
    const uint32_t rowA  = (uint32_t)((mw * 64 + (l & 15)) * 128);
    const uint32_t rowB0 = (uint32_t)((nw * 32 + ((l >> 4) << 3) + (l & 7)) * 128);

    float acc[4][4][4];
#pragma unroll
    for (int i = 0; i < 4; i++)
#pragma unroll
        for (int j = 0; j < 4; j++)
#pragma unroll
            for (int q = 0; q < 4; q++) acc[i][j][q] = 0.f;

    const int NC = K >> 6;

    cpa_tile(sb + A_OFF, A, lda, m0, 0, tid, 128);
    cpa_tile(sb + B_OFF, B, ldb, n0, 0, tid, 128);
    CP_COMMIT();
    if (NC > 1) {
        cpa_tile(sb + BUF_STRIDE + A_OFF, A, lda, m0, 64, tid, 128);
        cpa_tile(sb + BUF_STRIDE + B_OFF, B, ldb, n0, 64, tid, 128);
        CP_COMMIT();
    }

    for (int c = 0; c < NC; c++) {
        const uint32_t bufb = sb + (c % 3) * BUF_STRIDE;

        if (c + 1 < NC) CP_WAIT1(); else CP_WAIT0();
        __syncthreads();

        if (c + 2 < NC) {
            const uint32_t bn = sb + ((c + 2) % 3) * BUF_STRIDE;
            cpa_tile(bn + A_OFF, A, lda, m0, (c + 2) << 6, tid, 128);
            cpa_tile(bn + B_OFF, B, ldb, n0, (c + 2) << 6, tid, 128);
            CP_COMMIT();
        }

#pragma unroll
        for (int kk = 0; kk < 4; kk++) {
            const uint32_t kbB = ((uint32_t)(kk * 32) | bk) ^ swz;
            const uint32_t kbA = ((uint32_t)(kk * 32) | ak) ^ swz;

            uint32_t bh[8];
            const uint32_t bB = bufb + B_OFF + rowB0 + kbB;
            ldsm4(bh + 0, bB);
            ldsm4(bh + 4, bB + 16 * 128);

            const uint32_t aB = bufb + A_OFF + rowA + kbA;
#pragma unroll
            for (int mt = 0; mt < 4; mt++) {
                uint32_t ah[4];
                ldsm4(ah, aB + mt * 2048);
#pragma unroll
                for (int nt = 0; nt < 4; nt++) mma16816(acc[mt][nt], ah, bh + nt * 2);
            }
        }
    }

    const int row_base = m0 + mw * 64 + (l >> 2);
    const int col_base = n0 + nw * 32 + 2 * (l & 3);
#pragma unroll
    for (int mt = 0; mt < 4; mt++) {
        const int row = row_base + mt * 16;
#pragma unroll
        for (int nt = 0; nt < 4; nt++) {
            const int col = col_base + nt * 8;
            float2 bv = bias ? *(const float2*)(bias + col) : make_float2(0.f, 0.f);
            float r[4];
            r[0] = acc[mt][nt][0] + bv.x;  r[1] = acc[mt][nt][1] + bv.y;
            r[2] = acc[mt][nt][2] + bv.x;  r[3] = acc[mt][nt][3] + bv.y;
            if (relu) {
#pragma unroll
                for (int q = 0; q < 4; q++) r[q] = fmaxf(r[q], 0.f);
            }
            if (res) {
                const float2 e0 = *(const float2*)(res + cz + (size_t)row * ldc + col);
                const float2 e1 = *(const float2*)(res + cz + (size_t)(row + 8) * ldc + col);
                r[0] += e0.x; r[1] += e0.y; r[2] += e1.x; r[3] += e1.y;
            }
            if (C) {
                *(float2*)(C + cz + (size_t)row * ldc + col)       = make_float2(r[0], r[1]);
                *(float2*)(C + cz + (size_t)(row + 8) * ldc + col) = make_float2(r[2], r[3]);
            }
            if (Ch) {
                __half2 h0 = __floats2half2_rn(r[0], r[1]);
                __half2 h1 = __floats2half2_rn(r[2], r[3]);
                *(__half2*)(Ch + cz + (size_t)row * ldc + col)       = h0;
                *(__half2*)(Ch + cz + (size_t)(row + 8) * ldc + col) = h1;
            }
        }
    }
}

// ---------------------------------------------------------------------------
// narrow GEMM: BM=128, BN=64 (4m x 2n warps, 32x32 each), per-head V-mix.
// ---------------------------------------------------------------------------
#define NA_OFF 0
#define NB_OFF 16384
#define NBUF_STRIDE 24576
#define SMEM_GEMM_N (3 * NBUF_STRIDE)

__global__ __launch_bounds__(256, 2)
void gemm_n64(const f16* __restrict__ A, int lda, long zA,
              const f16* __restrict__ B, int ldb, long zB,
              const float* __restrict__ bias, int zBias,
              f16* __restrict__ Ch, int ldc, int zC,
              int K)
{
    extern __shared__ char smem[];
    const uint32_t sb = smem_u32(smem);

    const int tid = threadIdx.x;
    const int l   = tid & 31;
    const int w   = tid >> 5;
    const int mw  = w >> 1;
    const int nw  = w & 1;
    const int m0  = blockIdx.y * 128;
    const int z   = blockIdx.z;

    A += (long)z * zA;
    B += (long)z * zB;
    bias += (long)z * zBias;
    const size_t cz = (size_t)z * zC;

    const uint32_t swz  = (uint32_t)((l & 7) << 4);
    const uint32_t ak   = (uint32_t)((l >> 4) << 4);
    const uint32_t bk   = (uint32_t)(((l >> 3) & 1) << 4);
    const uint32_t rowA = (uint32_t)((mw * 32 + (l & 15)) * 128);
    uint32_t rowB[2];
#pragma unroll
    for (int nt2 = 0; nt2 < 2; nt2++)
        rowB[nt2] = (uint32_t)((nw * 32 + nt2 * 16 + ((l >> 4) << 3) + (l & 7)) * 128);

    float acc[2][4][4];
#pragma unroll
    for (int i = 0; i < 2; i++)
#pragma unroll
        for (int j = 0; j < 4; j++)
#pragma unroll
            for (int q = 0; q < 4; q++) acc[i][j][q] = 0.f;

    const int NC = K >> 6;

    cpa_tile(sb + NA_OFF, A, lda, m0, 0, tid, 128);
    cpa_tile(sb + NB_OFF, B, ldb, 0,  0, tid, 64);
    CP_COMMIT();
    if (NC > 1) {
        cpa_tile(sb + NBUF_STRIDE + NA_OFF, A, lda, m0, 64, tid, 128);
        cpa_tile(sb + NBUF_STRIDE + NB_OFF, B, ldb, 0,  64, tid, 64);
        CP_COMMIT();
    }

    for (int c = 0; c < NC; c++) {
        const uint32_t bufb = sb + (c % 3) * NBUF_STRIDE;

        if (c + 1 < NC) CP_WAIT1(); else CP_WAIT0();
        __syncthreads();

        if (c + 2 < NC) {
            const uint32_t bn = sb + ((c + 2) % 3) * NBUF_STRIDE;
            cpa_tile(bn + NA_OFF, A, lda, m0, (c + 2) << 6, tid, 128);
            cpa_tile(bn + NB_OFF, B, ldb, 0,  (c + 2) << 6, tid, 64);
            CP_COMMIT();
        }

#pragma unroll
        for (int kk = 0; kk < 4; kk++) {
            const uint32_t kbB = ((uint32_t)(kk * 32) | bk) ^ swz;
            const uint32_t kbA = ((uint32_t)(kk * 32) | ak) ^ swz;

            uint32_t bh[8];
            ldsm4(bh + 0, bufb + NB_OFF + rowB[0] + kbB);
            ldsm4(bh + 4, bufb + NB_OFF + rowB[1] + kbB);

            const uint32_t aB = bufb + NA_OFF + rowA + kbA;
#pragma unroll
            for (int mt = 0; mt < 2; mt++) {
                uint32_t ah[4];
                ldsm4(ah, aB + mt * 2048);
#pragma unroll
                for (int nt = 0; nt < 4; nt++) mma16816(acc[mt][nt], ah, bh + nt * 2);
            }
        }
    }

    const int row_base = m0 + mw * 32 + (l >> 2);
    const int col_base = nw * 32 + 2 * (l & 3);
#pragma unroll
    for (int mt = 0; mt < 2; mt++) {
        const int row = row_base + mt * 16;
#pragma unroll
        for (int nt = 0; nt < 4; nt++) {
            const int col = col_base + nt * 8;
            const float2 bv = *(const float2*)(bias + col);
            __half2 h0 = __floats2half2_rn(acc[mt][nt][0] + bv.x, acc[mt][nt][1] + bv.y);
            __half2 h1 = __floats2half2_rn(acc[mt][nt][2] + bv.x, acc[mt][nt][3] + bv.y);
            *(__half2*)(Ch + cz + (size_t)row * ldc + col)       = h0;
            *(__half2*)(Ch + cz + (size_t)(row + 8) * ldc + col) = h1;
        }
    }
}

// ---------------------------------------------------------------------------
// Attention core: block = query row m, warp = head h.
// ---------------------------------------------------------------------------
__global__ __launch_bounds__(256)
void attn_kernel(const f16* __restrict__ Qt, const float* __restrict__ key,
                 const float* __restrict__ value, f16* __restrict__ Y2)
{
    __shared__ float ks[8][512];
    __shared__ float vs[8][512];
    const int m = blockIdx.x;
    const int t = threadIdx.x;

    const float4* kg = (const float4*)(key   + (size_t)m * 8 * 512);
    const float4* vg = (const float4*)(value + (size_t)m * 8 * 512);
    float4* ksm = (float4*)ks;
    float4* vsm = (float4*)vs;
#pragma unroll
    for (int i = 0; i < 4; i++) {
        ksm[t + 256 * i] = kg[t + 256 * i];
        vsm[t + 256 * i] = vg[t + 256 * i];
    }
    __syncthreads();

    const int h = t >> 5, l = t & 31;

    const __half2* qtp = (const __half2*)(Qt + (size_t)m * 4096 + h * 512);
    float2 q2[8];
#pragma unroll
    for (int j = 0; j < 8; j++) q2[j] = __half22float2(qtp[l + 32 * j]);

    float s[8];
#pragma unroll
    for (int c = 0; c < 8; c++) {
        float p = 0.f;
#pragma unroll
        for (int j = 0; j < 8; j++) {
            const float2 kk = *(const float2*)&ks[c][64 * j + 2 * l];
            p += q2[j].x * kk.x + q2[j].y * kk.y;
        }
#pragma unroll
        for (int o = 16; o > 0; o >>= 1) p += __shfl_xor_sync(0xffffffffu, p, o);
        s[c] = p * 0.125f;
    }

    float mx = s[0];
#pragma unroll
    for (int c = 1; c < 8; c++) mx = fmaxf(mx, s[c]);
    float sum = 0.f;
#pragma unroll
    for (int c = 0; c < 8; c++) { s[c] = __expf(s[c] - mx); sum += s[c]; }
    const float inv = 1.f / sum;
#pragma unroll
    for (int c = 0; c < 8; c++) s[c] *= inv;

    __half2* yp = (__half2*)(Y2 + ((size_t)h * M_Q + m) * 512);
#pragma unroll
    for (int j = 0; j < 8; j++) {
        float2 a = make_float2(0.f, 0.f);
#pragma unroll
        for (int c = 0; c < 8; c++) {
            const float2 vv = *(const float2*)&vs[c][64 * j + 2 * l];
            a.x += s[c] * vv.x;
            a.y += s[c] * vv.y;
        }
        yp[l + 32 * j] = __floats2half2_rn(a.x, a.y);
    }
}

// ---------------------------------------------------------------------------
// LayerNorm(x [+ r]), H=512, one block per row; optional fp16 copy.
// ---------------------------------------------------------------------------
__global__ __launch_bounds__(256)
void ln_residual_kernel(const float* __restrict__ x, const float* __restrict__ r,
                        const float* __restrict__ g, const float* __restrict__ bt,
                        float* __restrict__ out, f16* __restrict__ oh)
{
    __shared__ float red[16];
    const int m = blockIdx.x;
    const int t = threadIdx.x;
    const int l = t & 31;
    const int w = t >> 5;
    const size_t base = (size_t)m * Hdim;

    float s0 = x[base + t];
    float s1 = x[base + t + 256];
    if (r) { s0 += r[base + t]; s1 += r[base + t + 256]; }

    float v = s0 + s1;
#pragma unroll
    for (int o = 16; o > 0; o >>= 1) v += __shfl_xor_sync(0xffffffffu, v, o);
    if (l == 0) red[w] = v;
    __syncthreads();
    float mean = 0.f;
#pragma unroll
    for (int i = 0; i < 8; i++) mean += red[i];
    mean *= (1.f / 512.f);

    const float d0 = s0 - mean, d1 = s1 - mean;
    float vv = d0 * d0 + d1 * d1;
#pragma unroll
    for (int o = 16; o > 0; o >>= 1) vv += __shfl_xor_sync(0xffffffffu, vv, o);
    if (l == 0) red[8 + w] = vv;
    __syncthreads();
    float var = 0.f;
#pragma unroll
    for (int i = 0; i < 8; i++) var += red[8 + i];
    var *= (1.f / 512.f);
    const float rstd = rsqrtf(var + 1e-5f);

    const float y0 = d0 * rstd * g[t]       + bt[t];
    const float y1 = d1 * rstd * g[t + 256] + bt[t + 256];
    out[base + t]       = y0;
    out[base + t + 256] = y1;
    if (oh) {
        oh[base + t]       = __float2half_rn(y0);
        oh[base + t + 256] = __float2half_rn(y1);
    }
}

// ---------------------------------------------------------------------------
extern "C" void kernel_launch(void* const* d_in, const int* in_sizes, int n_in,
                              void* d_out, int out_size)
{
    (void)in_sizes; (void)n_in; (void)out_size;
    const float* query = (const float*)d_in[0];
    const float* key   = (const float*)d_in[1];
    const float* value = (const float*)d_in[2];
    const float* Wq    = (const float*)d_in[3];
    const float* bq    = (const float*)d_in[4];
    const float* Wk    = (const float*)d_in[5];
    const float* Wv    = (const float*)d_in[7];
    const float* bv    = (const float*)d_in[8];
    const float* Wo    = (const float*)d_in[9];
    const float* bo    = (const float*)d_in[10];
    const float* ln1g  = (const float*)d_in[11];
    const float* ln1b  = (const float*)d_in[12];
    const float* W1    = (const float*)d_in[13];
    const float* b1    = (const float*)d_in[14];
    const float* W2    = (const float*)d_in[15];
    const float* b2    = (const float*)d_in[16];
    const float* ln2g  = (const float*)d_in[17];
    const float* ln2b  = (const float*)d_in[18];
    float* out = (float*)d_out;

    float *x, *h1;
    cudaGetSymbolAddress((void**)&x,  g_x);
    cudaGetSymbolAddress((void**)&h1, g_h1);

    f16 *q16,*Qp,*Qt,*Y2,*x16,*h1h,*f1h;
    f16 *wq,*wkT,*wv,*wo,*w1,*w2;
    cudaGetSymbolAddress((void**)&q16, g_q16);
    cudaGetSymbolAddress((void**)&Qp,  g_Qp16);
    cudaGetSymbolAddress((void**)&Qt,  g_Qt);
    cudaGetSymbolAddress((void**)&Y2,  g_Y2);
    cudaGetSymbolAddress((void**)&x16, g_x16);
    cudaGetSymbolAddress((void**)&h1h, g_h1h);
    cudaGetSymbolAddress((void**)&f1h, g_f1h);
    cudaGetSymbolAddress((void**)&wq,  g_wq16);
    cudaGetSymbolAddress((void**)&wkT, g_wkT);
    cudaGetSymbolAddress((void**)&wv,  g_wv16);
    cudaGetSymbolAddress((void**)&wo,  g_wo16);
    cudaGetSymbolAddress((void**)&w1,  g_w116);
    cudaGetSymbolAddress((void**)&w2,  g_w216);

    cudaFuncSetAttribute(gemm_std, cudaFuncAttributeMaxDynamicSharedMemorySize, SMEM_GEMM);
    cudaFuncSetAttribute(gemm_n64, cudaFuncAttributeMaxDynamicSharedMemorySize, SMEM_GEMM_N);

    // batched weight cvt (wq, wv, wo, w1, w2) in ONE launch
    {
        CvtTbl tbl;
        tbl.src[0] = (const float4*)Wq; tbl.dst[0] = (uint2*)wq;
        tbl.src[1] = (const float4*)Wv; tbl.dst[1] = (uint2*)wv;
        tbl.src[2] = (const float4*)Wo; tbl.dst[2] = (uint2*)wo;
        tbl.src[3] = (const float4*)W1; tbl.dst[3] = (uint2*)w1;
        tbl.src[4] = (const float4*)W2; tbl.dst[4] = (uint2*)w2;
        const int n0 = Hdim*Hdim/4, n1 = HF*Hdim/4;
        tbl.cum[0] = n0; tbl.cum[1] = 2*n0; tbl.cum[2] = 3*n0;
        tbl.cum[3] = 3*n0 + n1; tbl.cum[4] = 3*n0 + 2*n1;
        tbl.njobs = 5;
        cvt_batch<<<(tbl.cum[4] + 255)/256, 256>>>(tbl);
    }
    cvt_t16<<<dim3(16, 16), 256>>>(Wk, wkT, Hdim, Hdim);
    cvt_h16<<<(M_Q*Hdim/4 + 255)/256, 256>>>((const float4*)query, (uint2*)q16, M_Q*Hdim/4);

    // Qp = q16 @ Wq^T + bq  (fp16)
    gemm_std<<<dim3(4, 64, 1), 256, SMEM_GEMM>>>(
        q16, Hdim, 0, wq, Hdim, 0, bq, 0, 0, 0, Qp, Hdim, 0, Hdim, 0);

    // Qt_h = Qp_h @ Wk rows(h)  (grid.z = head, K=64)
    gemm_std<<<dim3(4, 64, 8), 256, SMEM_GEMM>>>(
        Qp, Hdim, 64, wkT, Hdim, 64, 0, 0, 0, 0, Qt, 8*Hdim, 512, 64, 0);

    // attention
    attn_kernel<<<M_Q, 256>>>(Qt, key, value, Y2);

    // x16_h = Y2_h @ Wv_h^T + bv_h
    gemm_n64<<<dim3(1, 64, 8), 256, SMEM_GEMM_N>>>(
        Y2, Hdim, (long)M_Q*Hdim, wv, Hdim, (long)64*Hdim, bv, 64,
        x16, Hdim, 64, Hdim);

    // O projection + query residual (fused) -> x ; LN1 -> h1 (+fp16)
    gemm_std<<<dim3(4, 64, 1), 256, SMEM_GEMM>>>(
        x16, Hdim, 0, wo, Hdim, 0, bo, 0, query, x, 0, Hdim, 0, Hdim, 0);
    ln_residual_kernel<<<M_Q, 256>>>(x, 0, ln1g, ln1b, h1, h1h);

    // FFN1 (relu, fp16) -> FFN2 + h1 residual (fused) -> x ; LN2 -> out
    gemm_std<<<dim3(8, 64, 1), 256, SMEM_GEMM>>>(
        h1h, Hdim, 0, w1, Hdim, 0, b1, 0, 0, 0, f1h, HF, 0, Hdim, 1);
    gemm_std<<<dim3(4, 64, 1), 256, SMEM_GEMM>>>(
        f1h, HF, 0, w2, HF, 0, b2, 0, h1, x, 0, Hdim, 0, HF, 0);
    ln_residual_kernel<<<M_Q, 256>>>(x, 0, ln2g, ln2b, out, 0);
}